// round 9
// baseline (speedup 1.0000x reference)
#include <cuda_runtime.h>
#include <cuda_bf16.h>
#include <float.h>

// Problem constants
#define BB 8
#define CC 64
#define NN 4096
#define KK 20
#define OO 64
#define BNK 655360.0f   // B*N*K

// ---------------- static scratch ----------------
__device__ float g_d2[(size_t)BB * NN * NN];          // 512 MB distance matrix
__device__ float g_z[(size_t)BB * NN * OO];           // W2 . x_m
__device__ float g_u[(size_t)BB * NN * OO];           // (W1-W2) . x_n + b
__device__ float g_ymax[(size_t)BB * NN * OO];        // u + max_k z
__device__ float g_sq[BB * NN];                       // |x_n|^2
__device__ int   g_idx[BB * NN * KK];                 // knn indices (within batch)
__device__ float g_sum[OO];
__device__ float g_sumsq[OO];
__device__ float g_scale[OO];
__device__ float g_shift[OO];

// ---------------- K_zero ----------------
__global__ void k_zero() {
    int t = threadIdx.x;
    if (t < OO) { g_sum[t] = 0.f; g_sumsq[t] = 0.f; }
}

// ---------------- K_prep: sq, z, u ----------------
__global__ __launch_bounds__(256) void k_prep(const float* __restrict__ x,
                                              const float* __restrict__ W,
                                              const float* __restrict__ bias) {
    __shared__ float xs[32][65];
    __shared__ float W2s[64][65];
    __shared__ float Wds[64][65];

    int blk = blockIdx.x;
    int b   = blk >> 7;
    int n0  = (blk & 127) * 32;
    int tid = threadIdx.x;

    for (int i = tid; i < 64 * 64; i += 256) {
        int o = i >> 6, c = i & 63;
        float w1 = W[o * 128 + c];
        float w2 = W[o * 128 + 64 + c];
        W2s[o][c] = w2;
        Wds[o][c] = w1 - w2;
    }
    const float* xb = x + (size_t)b * CC * NN;
    for (int i = tid; i < 64 * 32; i += 256) {
        int c = i >> 5, j = i & 31;
        xs[j][c] = xb[c * NN + n0 + j];
    }
    __syncthreads();

    if (tid < 32) {
        float s = 0.f;
        #pragma unroll 16
        for (int c = 0; c < 64; c++) { float v = xs[tid][c]; s += v * v; }
        g_sq[b * NN + n0 + tid] = s;
    }

    for (int i = tid; i < 32 * 64; i += 256) {
        int j = i >> 6, o = i & 63;
        float za = 0.f, ua = bias[o];
        #pragma unroll 16
        for (int c = 0; c < 64; c++) {
            float xv = xs[j][c];
            za = fmaf(W2s[o][c], xv, za);
            ua = fmaf(Wds[o][c], xv, ua);
        }
        size_t pt = (size_t)(b * NN + n0 + j) * OO + o;
        g_z[pt] = za;
        g_u[pt] = ua;
    }
}

// ---------------- K_dist: symmetric pairwise d2, FFMA2, pre-duplicated A ----------------
__global__ __launch_bounds__(256) void k_dist(const float* __restrict__ x) {
    int b  = blockIdx.z;
    int ti = blockIdx.y;          // q tile 0..31
    int tj = blockIdx.x;          // m tile 0..31
    if (tj < ti) return;
    bool diag = (tj == ti);

    __shared__ float sQd[32][256];   // q values duplicated pairwise: [2j]=[2j+1]=q_j
    __shared__ float sM[32][128];

    int q0 = ti * 128, m0 = tj * 128;
    int tid = threadIdx.x;
    int tx = tid & 15, ty = tid >> 4;

    unsigned long long acc[8][4];
    #pragma unroll
    for (int i = 0; i < 8; i++)
        #pragma unroll
        for (int j = 0; j < 4; j++) acc[i][j] = 0ull;

    for (int h = 0; h < 2; h++) {
        __syncthreads();
        const float* xb = x + ((size_t)b * CC + h * 32) * NN;
        for (int t = tid; t < 32 * 128; t += 256) {
            int c = t >> 7, n = t & 127;
            float qv = xb[c * NN + q0 + n];
            unsigned long long dup;
            asm("mov.b64 %0, {%1, %1};" : "=l"(dup) : "f"(qv));
            ((unsigned long long*)sQd[c])[n] = dup;
            sM[c][n] = xb[c * NN + m0 + n];
        }
        __syncthreads();

        #pragma unroll 8
        for (int c = 0; c < 32; c++) {
            const ulonglong2* aq = (const ulonglong2*)(sQd[c] + ty * 16);
            ulonglong2 a01 = aq[0], a23 = aq[1], a45 = aq[2], a67 = aq[3];
            ulonglong2 bb0 = *(const ulonglong2*)&sM[c][tx * 8];
            ulonglong2 bb1 = *(const ulonglong2*)&sM[c][tx * 8 + 4];
            unsigned long long B0 = bb0.x, B1 = bb0.y, B2 = bb1.x, B3 = bb1.y;
            unsigned long long Aa[8] = {a01.x, a01.y, a23.x, a23.y,
                                        a45.x, a45.y, a67.x, a67.y};
            #pragma unroll
            for (int i = 0; i < 8; i++) {
                asm("fma.rn.f32x2 %0, %1, %2, %3;" : "=l"(acc[i][0]) : "l"(Aa[i]), "l"(B0), "l"(acc[i][0]));
                asm("fma.rn.f32x2 %0, %1, %2, %3;" : "=l"(acc[i][1]) : "l"(Aa[i]), "l"(B1), "l"(acc[i][1]));
                asm("fma.rn.f32x2 %0, %1, %2, %3;" : "=l"(acc[i][2]) : "l"(Aa[i]), "l"(B2), "l"(acc[i][2]));
                asm("fma.rn.f32x2 %0, %1, %2, %3;" : "=l"(acc[i][3]) : "l"(Aa[i]), "l"(B3), "l"(acc[i][3]));
            }
        }
    }

    float d[8][8];
    #pragma unroll
    for (int i = 0; i < 8; i++)
        #pragma unroll
        for (int j = 0; j < 4; j++) {
            float lo, hi;
            asm("mov.b64 {%0, %1}, %2;" : "=f"(lo), "=f"(hi) : "l"(acc[i][j]));
            d[i][2 * j] = lo; d[i][2 * j + 1] = hi;
        }

    int qg0 = q0 + ty * 8, mg0 = m0 + tx * 8;
    float sqq[8], sqm[8];
    #pragma unroll
    for (int i = 0; i < 8; i++) {
        sqq[i] = g_sq[b * NN + qg0 + i];
        sqm[i] = g_sq[b * NN + mg0 + i];
    }
    #pragma unroll
    for (int i = 0; i < 8; i++)
        #pragma unroll
        for (int j = 0; j < 8; j++) {
            float v = (sqq[i] + sqm[j]) - 2.0f * d[i][j];
            d[i][j] = (diag && (qg0 + i == mg0 + j)) ? FLT_MAX : v;
        }

    float* base = g_d2 + ((size_t)b << 24);
    #pragma unroll
    for (int i = 0; i < 8; i++) {
        float* dst = base + (size_t)(qg0 + i) * NN + mg0;
        *(float4*)(dst)     = make_float4(d[i][0], d[i][1], d[i][2], d[i][3]);
        *(float4*)(dst + 4) = make_float4(d[i][4], d[i][5], d[i][6], d[i][7]);
    }
    if (!diag) {
        #pragma unroll
        for (int j = 0; j < 8; j++) {
            float* dst = base + (size_t)(mg0 + j) * NN + qg0;
            *(float4*)(dst)     = make_float4(d[0][j], d[1][j], d[2][j], d[3][j]);
            *(float4*)(dst + 4) = make_float4(d[4][j], d[5][j], d[6][j], d[7][j]);
        }
    }
}

// ---------------- K_select: warp per row, exact top-20 set, 2 passes ----------------
#define INS4(v) do { float t = (v); \
    float n0 = fminf(t, m0); t = fmaxf(t, m0); m0 = n0; \
    float n1 = fminf(t, m1); t = fmaxf(t, m1); m1 = n1; \
    float n2 = fminf(t, m2); t = fmaxf(t, m2); m2 = n2; \
    m3 = fminf(t, m3); } while (0)

// vote-compaction append of packed (valbits<<32 | idx) keys for v <= T
#define APPEND(vv, bidx) do { \
    bool h = ((vv) <= T); \
    unsigned mm = __ballot_sync(0xFFFFFFFFu, h); \
    if (mm) { \
        int pos = cnt + __popc(mm & lanemask_lt); \
        if (h && pos < 32) \
            qq[warp][pos] = ((unsigned long long)__float_as_uint(vv) << 32) | (unsigned)(bidx); \
        cnt += __popc(mm); \
    } } while (0)

__global__ __launch_bounds__(256) void k_select() {
    __shared__ unsigned long long qq[8][33];
    int warp = threadIdx.x >> 5;
    int row  = (blockIdx.x << 3) + warp;                 // b*N + n
    int lane = threadIdx.x & 31;
    unsigned lanemask_lt = (1u << lane) - 1u;
    const float4* dr4 = (const float4*)(g_d2 + (size_t)row * NN);

    // phase 1: per-lane sorted top-4 values
    float m0 = FLT_MAX, m1 = FLT_MAX, m2 = FLT_MAX, m3 = FLT_MAX;
    #pragma unroll 8
    for (int e = 0; e < 32; e++) {
        float4 v = dr4[e * 32 + lane];
        INS4(v.x); INS4(v.y); INS4(v.z); INS4(v.w);
    }

    // phase 2: 20 extraction rounds -> candidate threshold T
    float T = 0.f;
    for (int r = 0; r < KK; r++) {
        float w = m0;
        #pragma unroll
        for (int s = 16; s; s >>= 1)
            w = fminf(w, __shfl_xor_sync(0xFFFFFFFFu, w, s));
        unsigned msk = __ballot_sync(0xFFFFFFFFu, m0 == w);
        if (lane == __ffs(msk) - 1) {
            m0 = m1; m1 = m2; m2 = m3; m3 = FLT_MAX;
        }
        T = w;
    }

    // phase 3: single vote-compacted rescan collecting keys <= T
    int cnt = 0;
    #pragma unroll 4
    for (int e = 0; e < 32; e++) {
        float4 v = dr4[e * 32 + lane];
        int bi = e * 128 + lane * 4;
        APPEND(v.x, bi);
        APPEND(v.y, bi + 1);
        APPEND(v.z, bi + 2);
        APPEND(v.w, bi + 3);
    }
    __syncwarp();

    // classify: LT = count of strictly-less; exact iff LT < KK and queue fit
    unsigned Tb = __float_as_uint(T);
    unsigned long long key = (lane < cnt && cnt <= 32) ? qq[warp][lane]
                                                       : 0xFFFFFFFFFFFFFFFFull;
    bool less = (lane < cnt) && ((unsigned)(key >> 32) < Tb);
    bool eq   = (lane < cnt) && ((unsigned)(key >> 32) == Tb);
    unsigned lm = __ballot_sync(0xFFFFFFFFu, less);
    unsigned em = __ballot_sync(0xFFFFFFFFu, eq);
    int LT = __popc(lm);

    if (LT < KK && cnt <= 32) {
        // fast path: T is the true 20th value; write less, fill with ==T
        if (less) g_idx[row * KK + __popc(lm & lanemask_lt)] = (int)(key & 0xFFFFFFFFu);
        if (eq) {
            int s = LT + __popc(em & lanemask_lt);
            if (s < KK) g_idx[row * KK + s] = (int)(key & 0xFFFFFFFFu);
        }
    } else {
        // fallback (cache overflowed or tie explosion): exact packed-key extraction
        unsigned long long last = 0ull;
        for (int r = 0; r < KK; r++) {
            unsigned long long lmn = 0xFFFFFFFFFFFFFFFFull;
            #pragma unroll 4
            for (int e = 0; e < 32; e++) {
                float4 v = dr4[e * 32 + lane];
                unsigned bi = (unsigned)(e * 128 + lane * 4);
                unsigned long long k0 = ((unsigned long long)__float_as_uint(v.x) << 32) | bi;
                unsigned long long k1 = ((unsigned long long)__float_as_uint(v.y) << 32) | (bi + 1);
                unsigned long long k2 = ((unsigned long long)__float_as_uint(v.z) << 32) | (bi + 2);
                unsigned long long k3 = ((unsigned long long)__float_as_uint(v.w) << 32) | (bi + 3);
                if (k0 > last && k0 < lmn) lmn = k0;
                if (k1 > last && k1 < lmn) lmn = k1;
                if (k2 > last && k2 < lmn) lmn = k2;
                if (k3 > last && k3 < lmn) lmn = k3;
            }
            unsigned long long w = lmn;
            #pragma unroll
            for (int s = 16; s; s >>= 1) {
                unsigned long long o = __shfl_xor_sync(0xFFFFFFFFu, w, s);
                if (o < w) w = o;
            }
            if (lane == 0) g_idx[row * KK + r] = (int)(w & 0xFFFFFFFFu);
            last = w;
        }
    }
}

// ---------------- K_gather: ymax + BN stats ----------------
__global__ __launch_bounds__(256) void k_gather() {
    __shared__ float s[256];
    int tid = threadIdx.x;
    int pl = tid >> 6, o = tid & 63;
    float rs1 = 0.f, rs2 = 0.f;

    #pragma unroll
    for (int it = 0; it < 4; it++) {
        int pt = blockIdx.x * 16 + it * 4 + pl;
        int zbase = pt & ~(NN - 1);
        float u = g_u[(size_t)pt * OO + o];
        float m = -FLT_MAX, s1 = 0.f, s2 = 0.f;
        #pragma unroll
        for (int k = 0; k < KK; k++) {
            int nbr = __ldg(&g_idx[pt * KK + k]);
            float z = g_z[(size_t)(zbase + nbr) * OO + o];
            m = fmaxf(m, z);
            s1 += z;
            s2 = fmaf(z, z, s2);
        }
        g_ymax[(size_t)pt * OO + o] = u + m;
        rs1 += 20.f * u + s1;
        rs2 += fmaf(20.f * u, u, fmaf(2.f * u, s1, s2));
    }
    s[tid] = rs1; __syncthreads();
    if (pl == 0) atomicAdd(&g_sum[o], s[o] + s[o + 64] + s[o + 128] + s[o + 192]);
    __syncthreads();
    s[tid] = rs2; __syncthreads();
    if (pl == 0) atomicAdd(&g_sumsq[o], s[o] + s[o + 64] + s[o + 128] + s[o + 192]);
}

// ---------------- K_stats ----------------
__global__ void k_stats(const float* __restrict__ gamma, const float* __restrict__ beta) {
    int o = threadIdx.x;
    if (o < OO) {
        float mean = g_sum[o] / BNK;
        float var  = g_sumsq[o] / BNK - mean * mean;
        float sc   = gamma[o] * rsqrtf(var + 1e-5f);
        g_scale[o] = sc;
        g_shift[o] = beta[o] - mean * sc;
    }
}

// ---------------- K_final ----------------
__global__ __launch_bounds__(256) void k_final(float* __restrict__ out) {
    __shared__ float t[64][33];
    int b  = blockIdx.x >> 7;
    int n0 = (blockIdx.x & 127) << 5;
    int tid = threadIdx.x;

    for (int i = tid; i < 2048; i += 256) {
        int r = i >> 6, c = i & 63;
        t[c][r] = g_ymax[(size_t)((b << 12) + n0 + r) * OO + c];
    }
    __syncthreads();
    for (int i = tid; i < 2048; i += 256) {
        int o = i >> 5, nl = i & 31;
        float v = fmaf(t[o][nl], g_scale[o], g_shift[o]);
        out[(size_t)b * OO * NN + (size_t)o * NN + n0 + nl] = fmaxf(v, 0.f);
    }
}

// ---------------- launch ----------------
extern "C" void kernel_launch(void* const* d_in, const int* in_sizes, int n_in,
                              void* d_out, int out_size) {
    const float* x     = (const float*)d_in[0];
    const float* W     = (const float*)d_in[1];
    const float* bias  = (const float*)d_in[2];
    const float* gamma = (const float*)d_in[3];
    const float* beta  = (const float*)d_in[4];
    float* out = (float*)d_out;

    k_zero<<<1, 128>>>();
    k_prep<<<1024, 256>>>(x, W, bias);
    dim3 gd(32, 32, BB);
    k_dist<<<gd, 256>>>(x);
    k_select<<<BB * NN / 8, 256>>>();
    k_gather<<<2048, 256>>>();
    k_stats<<<1, 64>>>(gamma, beta);
    k_final<<<1024, 256>>>(out);
}

// round 10
// speedup vs baseline: 1.1667x; 1.1667x over previous
#include <cuda_runtime.h>
#include <cuda_bf16.h>
#include <float.h>

// Problem constants
#define BB 8
#define CC 64
#define NN 4096
#define KK 20
#define OO 64
#define BNK 655360.0f   // B*N*K

// ---------------- static scratch ----------------
__device__ float         g_d2 [(size_t)BB * NN * NN];   // 512 MB fp32 distances
__device__ __nv_bfloat16 g_d2h[(size_t)BB * NN * NN];   // 268 MB bf16 shadow
__device__ float g_z[(size_t)BB * NN * OO];
__device__ float g_u[(size_t)BB * NN * OO];
__device__ float g_ymax[(size_t)BB * NN * OO];
__device__ float g_sq[BB * NN];
__device__ int   g_idx[BB * NN * KK];
__device__ float g_sum[OO];
__device__ float g_sumsq[OO];

// ---------------- K_prep: sq, z, u (+ zero stats) ----------------
__global__ __launch_bounds__(256) void k_prep(const float* __restrict__ x,
                                              const float* __restrict__ W,
                                              const float* __restrict__ bias) {
    __shared__ float xs[32][65];
    __shared__ float W2s[64][65];
    __shared__ float Wds[64][65];

    int blk = blockIdx.x;
    int b   = blk >> 7;
    int n0  = (blk & 127) * 32;
    int tid = threadIdx.x;

    if (blk == 0 && tid < OO) { g_sum[tid] = 0.f; g_sumsq[tid] = 0.f; }

    for (int i = tid; i < 64 * 64; i += 256) {
        int o = i >> 6, c = i & 63;
        float w1 = W[o * 128 + c];
        float w2 = W[o * 128 + 64 + c];
        W2s[o][c] = w2;
        Wds[o][c] = w1 - w2;
    }
    const float* xb = x + (size_t)b * CC * NN;
    for (int i = tid; i < 64 * 32; i += 256) {
        int c = i >> 5, j = i & 31;
        xs[j][c] = xb[c * NN + n0 + j];
    }
    __syncthreads();

    if (tid < 32) {
        float s = 0.f;
        #pragma unroll 16
        for (int c = 0; c < 64; c++) { float v = xs[tid][c]; s += v * v; }
        g_sq[b * NN + n0 + tid] = s;
    }

    for (int i = tid; i < 32 * 64; i += 256) {
        int j = i >> 6, o = i & 63;
        float za = 0.f, ua = bias[o];
        #pragma unroll 16
        for (int c = 0; c < 64; c++) {
            float xv = xs[j][c];
            za = fmaf(W2s[o][c], xv, za);
            ua = fmaf(Wds[o][c], xv, ua);
        }
        size_t pt = (size_t)(b * NN + n0 + j) * OO + o;
        g_z[pt] = za;
        g_u[pt] = ua;
    }
}

// ---------------- K_dist: symmetric pairwise d2, FFMA2 (R7 core) + bf16 shadow ----------------
__global__ __launch_bounds__(256) void k_dist(const float* __restrict__ x) {
    int b  = blockIdx.z;
    int ti = blockIdx.y;
    int tj = blockIdx.x;
    if (tj < ti) return;
    bool diag = (tj == ti);

    __shared__ float sQ[32][128];
    __shared__ float sM[32][128];

    int q0 = ti * 128, m0 = tj * 128;
    int tid = threadIdx.x;
    int tx = tid & 15, ty = tid >> 4;

    unsigned long long acc[8][4];
    #pragma unroll
    for (int i = 0; i < 8; i++)
        #pragma unroll
        for (int j = 0; j < 4; j++) acc[i][j] = 0ull;

    for (int h = 0; h < 2; h++) {
        __syncthreads();
        const float* xb = x + ((size_t)b * CC + h * 32) * NN;
        for (int t = tid; t < 32 * 128; t += 256) {
            int c = t >> 7, n = t & 127;
            sQ[c][n] = xb[c * NN + q0 + n];
            sM[c][n] = xb[c * NN + m0 + n];
        }
        __syncthreads();

        #pragma unroll 8
        for (int c = 0; c < 32; c++) {
            float4 a0 = *(const float4*)&sQ[c][ty * 8];
            float4 a1 = *(const float4*)&sQ[c][ty * 8 + 4];
            ulonglong2 bb0 = *(const ulonglong2*)&sM[c][tx * 8];
            ulonglong2 bb1 = *(const ulonglong2*)&sM[c][tx * 8 + 4];
            unsigned long long B0 = bb0.x, B1 = bb0.y, B2 = bb1.x, B3 = bb1.y;
            float av[8] = {a0.x, a0.y, a0.z, a0.w, a1.x, a1.y, a1.z, a1.w};
            #pragma unroll
            for (int i = 0; i < 8; i++) {
                unsigned long long A;
                asm("mov.b64 %0, {%1, %1};" : "=l"(A) : "f"(av[i]));
                asm("fma.rn.f32x2 %0, %1, %2, %3;" : "=l"(acc[i][0]) : "l"(A), "l"(B0), "l"(acc[i][0]));
                asm("fma.rn.f32x2 %0, %1, %2, %3;" : "=l"(acc[i][1]) : "l"(A), "l"(B1), "l"(acc[i][1]));
                asm("fma.rn.f32x2 %0, %1, %2, %3;" : "=l"(acc[i][2]) : "l"(A), "l"(B2), "l"(acc[i][2]));
                asm("fma.rn.f32x2 %0, %1, %2, %3;" : "=l"(acc[i][3]) : "l"(A), "l"(B3), "l"(acc[i][3]));
            }
        }
    }

    float d[8][8];
    #pragma unroll
    for (int i = 0; i < 8; i++)
        #pragma unroll
        for (int j = 0; j < 4; j++) {
            float lo, hi;
            asm("mov.b64 {%0, %1}, %2;" : "=f"(lo), "=f"(hi) : "l"(acc[i][j]));
            d[i][2 * j] = lo; d[i][2 * j + 1] = hi;
        }

    int qg0 = q0 + ty * 8, mg0 = m0 + tx * 8;
    float sqq[8], sqm[8];
    #pragma unroll
    for (int i = 0; i < 8; i++) {
        sqq[i] = g_sq[b * NN + qg0 + i];
        sqm[i] = g_sq[b * NN + mg0 + i];
    }
    #pragma unroll
    for (int i = 0; i < 8; i++)
        #pragma unroll
        for (int j = 0; j < 8; j++) {
            float v = (sqq[i] + sqm[j]) - 2.0f * d[i][j];
            d[i][j] = (diag && (qg0 + i == mg0 + j)) ? FLT_MAX : v;
        }

    float* base = g_d2 + ((size_t)b << 24);
    __nv_bfloat16* hbase = g_d2h + ((size_t)b << 24);
    #pragma unroll
    for (int i = 0; i < 8; i++) {
        float* dst = base + (size_t)(qg0 + i) * NN + mg0;
        *(float4*)(dst)     = make_float4(d[i][0], d[i][1], d[i][2], d[i][3]);
        *(float4*)(dst + 4) = make_float4(d[i][4], d[i][5], d[i][6], d[i][7]);
        uint4 pk;
        __nv_bfloat162 h0 = __floats2bfloat162_rn(d[i][0], d[i][1]);
        __nv_bfloat162 h1 = __floats2bfloat162_rn(d[i][2], d[i][3]);
        __nv_bfloat162 h2 = __floats2bfloat162_rn(d[i][4], d[i][5]);
        __nv_bfloat162 h3 = __floats2bfloat162_rn(d[i][6], d[i][7]);
        pk.x = *(unsigned*)&h0; pk.y = *(unsigned*)&h1;
        pk.z = *(unsigned*)&h2; pk.w = *(unsigned*)&h3;
        *(uint4*)(hbase + (size_t)(qg0 + i) * NN + mg0) = pk;
    }
    if (!diag) {
        #pragma unroll
        for (int j = 0; j < 8; j++) {
            float* dst = base + (size_t)(mg0 + j) * NN + qg0;
            *(float4*)(dst)     = make_float4(d[0][j], d[1][j], d[2][j], d[3][j]);
            *(float4*)(dst + 4) = make_float4(d[4][j], d[5][j], d[6][j], d[7][j]);
            uint4 pk;
            __nv_bfloat162 h0 = __floats2bfloat162_rn(d[0][j], d[1][j]);
            __nv_bfloat162 h1 = __floats2bfloat162_rn(d[2][j], d[3][j]);
            __nv_bfloat162 h2 = __floats2bfloat162_rn(d[4][j], d[5][j]);
            __nv_bfloat162 h3 = __floats2bfloat162_rn(d[6][j], d[7][j]);
            pk.x = *(unsigned*)&h0; pk.y = *(unsigned*)&h1;
            pk.z = *(unsigned*)&h2; pk.w = *(unsigned*)&h3;
            *(uint4*)(hbase + (size_t)(mg0 + j) * NN + qg0) = pk;
        }
    }
}

// ---------------- K_select: bf16 screen + fp32 refine, exact top-20 set ----------------
#define INSP(v) do { __nv_bfloat162 t = (v); \
    __nv_bfloat162 n0 = __hmin2(t, p0); t = __hmax2(t, p0); p0 = n0; \
    __nv_bfloat162 n1 = __hmin2(t, p1); t = __hmax2(t, p1); p1 = n1; \
    __nv_bfloat162 n2 = __hmin2(t, p2); t = __hmax2(t, p2); p2 = n2; \
    p3 = __hmin2(t, p3); } while (0)

#define CAS(x, y) do { float _t = fminf(x, y); y = fmaxf(x, y); x = _t; } while (0)

__global__ __launch_bounds__(256) void k_select() {
    __shared__ int qq[8][36];
    int warp = threadIdx.x >> 5;
    int row  = (blockIdx.x << 3) + warp;                 // b*N + n
    int lane = threadIdx.x & 31;
    unsigned ltmask = (1u << lane) - 1u;
    const uint4* hr4 = (const uint4*)(g_d2h + (size_t)row * NN);

    // phase 1: packed bf16x2 top-4 per half-lane (depth 8 total)
    unsigned inf2b = 0x7F807F80u;
    __nv_bfloat162 p0, p1, p2, p3;
    p0 = p1 = p2 = p3 = *reinterpret_cast<__nv_bfloat162*>(&inf2b);
    #pragma unroll 4
    for (int e = 0; e < 16; e++) {
        uint4 r = hr4[e * 32 + lane];
        __nv_bfloat162 v0 = *reinterpret_cast<__nv_bfloat162*>(&r.x);
        __nv_bfloat162 v1 = *reinterpret_cast<__nv_bfloat162*>(&r.y);
        __nv_bfloat162 v2 = *reinterpret_cast<__nv_bfloat162*>(&r.z);
        __nv_bfloat162 v3 = *reinterpret_cast<__nv_bfloat162*>(&r.w);
        INSP(v0); INSP(v1); INSP(v2); INSP(v3);
    }

    // bitonic merge of two sorted-4 chains -> sorted 8
    float a0 = __low2float(p0),  a1 = __low2float(p1);
    float a2 = __low2float(p2),  a3 = __low2float(p3);
    float a4 = __high2float(p3), a5 = __high2float(p2);
    float a6 = __high2float(p1), a7 = __high2float(p0);
    CAS(a0, a4); CAS(a1, a5); CAS(a2, a6); CAS(a3, a7);
    CAS(a0, a2); CAS(a1, a3); CAS(a4, a6); CAS(a5, a7);
    CAS(a0, a1); CAS(a2, a3); CAS(a4, a5); CAS(a6, a7);

    // phase 2: 20 extraction rounds -> candidate bf16 threshold T
    float T = 0.f;
    for (int r = 0; r < KK; r++) {
        float w = a0;
        #pragma unroll
        for (int s = 16; s; s >>= 1)
            w = fminf(w, __shfl_xor_sync(0xFFFFFFFFu, w, s));
        unsigned msk = __ballot_sync(0xFFFFFFFFu, a0 == w);
        if (lane == __ffs(msk) - 1) {
            a0 = a1; a1 = a2; a2 = a3; a3 = a4;
            a4 = a5; a5 = a6; a6 = a7; a7 = FLT_MAX;
        }
        T = w;
    }

    // pass A: packed counts of (<=T) and (<T), plus active-iter bitmap
    __nv_bfloat16  tb = __float2bfloat16(T);
    __nv_bfloat162 Tp = __bfloat162bfloat162(tb);
    __nv_bfloat162 zero2 = __floats2bfloat162_rn(0.f, 0.f);
    __nv_bfloat162 accLE = zero2, accLT = zero2;
    unsigned bm = 0;
    #pragma unroll 4
    for (int e = 0; e < 16; e++) {
        uint4 r = hr4[e * 32 + lane];
        __nv_bfloat162 v0 = *reinterpret_cast<__nv_bfloat162*>(&r.x);
        __nv_bfloat162 v1 = *reinterpret_cast<__nv_bfloat162*>(&r.y);
        __nv_bfloat162 v2 = *reinterpret_cast<__nv_bfloat162*>(&r.z);
        __nv_bfloat162 v3 = *reinterpret_cast<__nv_bfloat162*>(&r.w);
        __nv_bfloat162 s = __hadd2(__hadd2(__hle2(v0, Tp), __hle2(v1, Tp)),
                                   __hadd2(__hle2(v2, Tp), __hle2(v3, Tp)));
        accLE = __hadd2(accLE, s);
        accLT = __hadd2(accLT, __hadd2(__hadd2(__hlt2(v0, Tp), __hlt2(v1, Tp)),
                                       __hadd2(__hlt2(v2, Tp), __hlt2(v3, Tp))));
        if (__low2float(s) + __high2float(s) > 0.f) bm |= 1u << e;
    }
    float2 fle = __bfloat1622float2(accLE);
    float2 flt = __bfloat1622float2(accLT);
    int lec = (int)(fle.x + fle.y);
    int ltc = (int)(flt.x + flt.y);
    int packed = (ltc << 16) | lec;
    int pre = packed;
    #pragma unroll
    for (int s = 1; s < 32; s <<= 1) {
        int n = __shfl_up_sync(0xFFFFFFFFu, pre, s);
        if (lane >= s) pre += n;
    }
    int tot   = __shfl_sync(0xFFFFFFFFu, pre, 31);
    int LEtot = tot & 0xFFFF, LTtot = tot >> 16;
    int off   = (pre - packed) & 0xFFFF;       // exclusive prefix of LE hits

    if (LTtot < KK && LEtot >= KK && LEtot <= 32) {
        // pass B: write candidate indices (only active iters; L1-hot)
        while (bm) {
            int e = __ffs(bm) - 1; bm &= bm - 1;
            uint4 r = hr4[e * 32 + lane];
            int base = (e * 32 + lane) * 8;
            __nv_bfloat162 v0 = *reinterpret_cast<__nv_bfloat162*>(&r.x);
            __nv_bfloat162 v1 = *reinterpret_cast<__nv_bfloat162*>(&r.y);
            __nv_bfloat162 v2 = *reinterpret_cast<__nv_bfloat162*>(&r.z);
            __nv_bfloat162 v3 = *reinterpret_cast<__nv_bfloat162*>(&r.w);
            if (__low2float(v0)  <= T) qq[warp][off++] = base;
            if (__high2float(v0) <= T) qq[warp][off++] = base + 1;
            if (__low2float(v1)  <= T) qq[warp][off++] = base + 2;
            if (__high2float(v1) <= T) qq[warp][off++] = base + 3;
            if (__low2float(v2)  <= T) qq[warp][off++] = base + 4;
            if (__high2float(v2) <= T) qq[warp][off++] = base + 5;
            if (__low2float(v3)  <= T) qq[warp][off++] = base + 6;
            if (__high2float(v3) <= T) qq[warp][off++] = base + 7;
        }
        __syncwarp();

        // fp32 refine: fetch candidates, exclude (cnt-20) largest keys
        unsigned long long key = 0ull;
        if (lane < LEtot) {
            int idx = qq[warp][lane];
            unsigned vb = __float_as_uint(g_d2[(size_t)row * NN + idx]);
            unsigned u  = (vb & 0x80000000u) ? ~vb : (vb | 0x80000000u);
            key = ((unsigned long long)u << 32) | (unsigned)idx;
        }
        int rem = LEtot - KK;
        for (int r = 0; r < rem; r++) {
            unsigned long long w = key;
            #pragma unroll
            for (int s = 16; s; s >>= 1) {
                unsigned long long o = __shfl_xor_sync(0xFFFFFFFFu, w, s);
                if (o > w) w = o;
            }
            unsigned msk = __ballot_sync(0xFFFFFFFFu, key == w);
            if (lane == __ffs(msk) - 1) key = 0ull;
        }
        unsigned vm = __ballot_sync(0xFFFFFFFFu, key != 0ull);
        if (key) g_idx[row * KK + __popc(vm & ltmask)] = (int)(key & 0xFFFFFFFFu);
    } else {
        // fallback: exact fp32 packed-key extraction (rare)
        const float4* dr4 = (const float4*)(g_d2 + (size_t)row * NN);
        unsigned long long last = 0ull;
        for (int r = 0; r < KK; r++) {
            unsigned long long lmn = 0xFFFFFFFFFFFFFFFFull;
            #pragma unroll 4
            for (int e = 0; e < 32; e++) {
                float4 v = dr4[e * 32 + lane];
                unsigned bi = (unsigned)(e * 128 + lane * 4);
                unsigned long long k0 = ((unsigned long long)__float_as_uint(v.x) << 32) | bi;
                unsigned long long k1 = ((unsigned long long)__float_as_uint(v.y) << 32) | (bi + 1);
                unsigned long long k2 = ((unsigned long long)__float_as_uint(v.z) << 32) | (bi + 2);
                unsigned long long k3 = ((unsigned long long)__float_as_uint(v.w) << 32) | (bi + 3);
                if (k0 > last && k0 < lmn) lmn = k0;
                if (k1 > last && k1 < lmn) lmn = k1;
                if (k2 > last && k2 < lmn) lmn = k2;
                if (k3 > last && k3 < lmn) lmn = k3;
            }
            unsigned long long w = lmn;
            #pragma unroll
            for (int s = 16; s; s >>= 1) {
                unsigned long long o = __shfl_xor_sync(0xFFFFFFFFu, w, s);
                if (o < w) w = o;
            }
            if (lane == 0) g_idx[row * KK + r] = (int)(w & 0xFFFFFFFFu);
            last = w;
        }
    }
}

// ---------------- K_gather: ymax + BN stats ----------------
__global__ __launch_bounds__(256) void k_gather() {
    __shared__ float s[256];
    int tid = threadIdx.x;
    int pl = tid >> 6, o = tid & 63;
    float rs1 = 0.f, rs2 = 0.f;

    #pragma unroll
    for (int it = 0; it < 4; it++) {
        int pt = blockIdx.x * 16 + it * 4 + pl;
        int zbase = pt & ~(NN - 1);
        float u = g_u[(size_t)pt * OO + o];
        float m = -FLT_MAX, s1 = 0.f, s2 = 0.f;
        #pragma unroll
        for (int k = 0; k < KK; k++) {
            int nbr = __ldg(&g_idx[pt * KK + k]);
            float z = g_z[(size_t)(zbase + nbr) * OO + o];
            m = fmaxf(m, z);
            s1 += z;
            s2 = fmaf(z, z, s2);
        }
        g_ymax[(size_t)pt * OO + o] = u + m;
        rs1 += 20.f * u + s1;
        rs2 += fmaf(20.f * u, u, fmaf(2.f * u, s1, s2));
    }
    s[tid] = rs1; __syncthreads();
    if (pl == 0) atomicAdd(&g_sum[o], s[o] + s[o + 64] + s[o + 128] + s[o + 192]);
    __syncthreads();
    s[tid] = rs2; __syncthreads();
    if (pl == 0) atomicAdd(&g_sumsq[o], s[o] + s[o + 64] + s[o + 128] + s[o + 192]);
}

// ---------------- K_final: stats + normalize + relu + transpose ----------------
__global__ __launch_bounds__(256) void k_final(const float* __restrict__ gamma,
                                               const float* __restrict__ beta,
                                               float* __restrict__ out) {
    __shared__ float t[64][33];
    __shared__ float ssc[64], ssh[64];
    int b  = blockIdx.x >> 7;
    int n0 = (blockIdx.x & 127) << 5;
    int tid = threadIdx.x;

    if (tid < 64) {
        float mean = g_sum[tid] / BNK;
        float var  = g_sumsq[tid] / BNK - mean * mean;
        float sc   = gamma[tid] * rsqrtf(var + 1e-5f);
        ssc[tid] = sc;
        ssh[tid] = beta[tid] - mean * sc;
    }
    for (int i = tid; i < 2048; i += 256) {
        int r = i >> 6, c = i & 63;
        t[c][r] = g_ymax[(size_t)((b << 12) + n0 + r) * OO + c];
    }
    __syncthreads();
    for (int i = tid; i < 2048; i += 256) {
        int o = i >> 5, nl = i & 31;
        float v = fmaf(t[o][nl], ssc[o], ssh[o]);
        out[(size_t)b * OO * NN + (size_t)o * NN + n0 + nl] = fmaxf(v, 0.f);
    }
}

// ---------------- launch ----------------
extern "C" void kernel_launch(void* const* d_in, const int* in_sizes, int n_in,
                              void* d_out, int out_size) {
    const float* x     = (const float*)d_in[0];
    const float* W     = (const float*)d_in[1];
    const float* bias  = (const float*)d_in[2];
    const float* gamma = (const float*)d_in[3];
    const float* beta  = (const float*)d_in[4];
    float* out = (float*)d_out;

    k_prep<<<1024, 256>>>(x, W, bias);
    dim3 gd(32, 32, BB);
    k_dist<<<gd, 256>>>(x);
    k_select<<<BB * NN / 8, 256>>>();
    k_gather<<<2048, 256>>>();
    k_final<<<1024, 256>>>(gamma, beta, out);
}

// round 11
// speedup vs baseline: 1.3585x; 1.1643x over previous
#include <cuda_runtime.h>
#include <cuda_bf16.h>
#include <float.h>

// Problem constants
#define BB 8
#define CC 64
#define NN 4096
#define KK 20
#define OO 64
#define BNK 655360.0f   // B*N*K

// ---------------- static scratch ----------------
__device__ __nv_bfloat16 g_d2h[(size_t)BB * NN * NN];   // 268 MB truncated-bf16 distances
__device__ float g_xt[(size_t)BB * NN * CC];            // point-major x (8 MB, L2-resident)
__device__ float g_z[(size_t)BB * NN * OO];
__device__ float g_u[(size_t)BB * NN * OO];
__device__ float g_ymax[(size_t)BB * NN * OO];
__device__ float g_sq[BB * NN];
__device__ int   g_idx[BB * NN * KK];
__device__ float g_sum[OO];
__device__ float g_sumsq[OO];

// exact fp32 distance recompute from x_t (q, m within-batch; zbase = b*NN)
__device__ __forceinline__ float recompute_d(int row, int zbase, int m) {
    const float4* xq = (const float4*)(g_xt + (size_t)row * CC);
    const float4* xc = (const float4*)(g_xt + (size_t)(zbase + m) * CC);
    float acc = 0.f;
    #pragma unroll
    for (int c = 0; c < 16; c++) {
        float4 a = xq[c], b = xc[c];
        acc = fmaf(a.x, b.x, acc);
        acc = fmaf(a.y, b.y, acc);
        acc = fmaf(a.z, b.z, acc);
        acc = fmaf(a.w, b.w, acc);
    }
    return (g_sq[row] + g_sq[zbase + m]) - 2.0f * acc;
}

__device__ __forceinline__ unsigned long long sortable_key(float d, unsigned idx) {
    unsigned vb = __float_as_uint(d);
    unsigned u  = (vb & 0x80000000u) ? ~vb : (vb | 0x80000000u);
    return ((unsigned long long)u << 32) | idx;
}

// ---------------- K_prep: sq, z, u, x_t (+ zero stats) ----------------
__global__ __launch_bounds__(256) void k_prep(const float* __restrict__ x,
                                              const float* __restrict__ W,
                                              const float* __restrict__ bias) {
    __shared__ float xs[32][65];
    __shared__ float W2s[64][65];
    __shared__ float Wds[64][65];

    int blk = blockIdx.x;
    int b   = blk >> 7;
    int n0  = (blk & 127) * 32;
    int tid = threadIdx.x;

    if (blk == 0 && tid < OO) { g_sum[tid] = 0.f; g_sumsq[tid] = 0.f; }

    for (int i = tid; i < 64 * 64; i += 256) {
        int o = i >> 6, c = i & 63;
        float w1 = W[o * 128 + c];
        float w2 = W[o * 128 + 64 + c];
        W2s[o][c] = w2;
        Wds[o][c] = w1 - w2;
    }
    const float* xb = x + (size_t)b * CC * NN;
    for (int i = tid; i < 64 * 32; i += 256) {
        int c = i >> 5, j = i & 31;
        xs[j][c] = xb[c * NN + n0 + j];
    }
    __syncthreads();

    if (tid < 32) {
        float s = 0.f;
        #pragma unroll 16
        for (int c = 0; c < 64; c++) { float v = xs[tid][c]; s += v * v; }
        g_sq[b * NN + n0 + tid] = s;
    }

    // point-major x copy for refine recompute
    for (int i = tid; i < 2048; i += 256) {
        int j = i >> 6, c = i & 63;
        g_xt[(size_t)(b * NN + n0 + j) * CC + c] = xs[j][c];
    }

    for (int i = tid; i < 32 * 64; i += 256) {
        int j = i >> 6, o = i & 63;
        float za = 0.f, ua = bias[o];
        #pragma unroll 16
        for (int c = 0; c < 64; c++) {
            float xv = xs[j][c];
            za = fmaf(W2s[o][c], xv, za);
            ua = fmaf(Wds[o][c], xv, ua);
        }
        size_t pt = (size_t)(b * NN + n0 + j) * OO + o;
        g_z[pt] = za;
        g_u[pt] = ua;
    }
}

// ---------------- K_dist: symmetric pairwise d2, FFMA2, bf16-truncated output only ----------------
__global__ __launch_bounds__(256) void k_dist(const float* __restrict__ x) {
    int b  = blockIdx.z;
    int ti = blockIdx.y;
    int tj = blockIdx.x;
    if (tj < ti) return;
    bool diag = (tj == ti);

    __shared__ float sQ[32][128];
    __shared__ float sM[32][128];

    int q0 = ti * 128, m0 = tj * 128;
    int tid = threadIdx.x;
    int tx = tid & 15, ty = tid >> 4;

    unsigned long long acc[8][4];
    #pragma unroll
    for (int i = 0; i < 8; i++)
        #pragma unroll
        for (int j = 0; j < 4; j++) acc[i][j] = 0ull;

    for (int h = 0; h < 2; h++) {
        __syncthreads();
        const float* xb = x + ((size_t)b * CC + h * 32) * NN;
        for (int t = tid; t < 32 * 128; t += 256) {
            int c = t >> 7, n = t & 127;
            sQ[c][n] = xb[c * NN + q0 + n];
            sM[c][n] = xb[c * NN + m0 + n];
        }
        __syncthreads();

        #pragma unroll 8
        for (int c = 0; c < 32; c++) {
            float4 a0 = *(const float4*)&sQ[c][ty * 8];
            float4 a1 = *(const float4*)&sQ[c][ty * 8 + 4];
            ulonglong2 bb0 = *(const ulonglong2*)&sM[c][tx * 8];
            ulonglong2 bb1 = *(const ulonglong2*)&sM[c][tx * 8 + 4];
            unsigned long long B0 = bb0.x, B1 = bb0.y, B2 = bb1.x, B3 = bb1.y;
            float av[8] = {a0.x, a0.y, a0.z, a0.w, a1.x, a1.y, a1.z, a1.w};
            #pragma unroll
            for (int i = 0; i < 8; i++) {
                unsigned long long A;
                asm("mov.b64 %0, {%1, %1};" : "=l"(A) : "f"(av[i]));
                asm("fma.rn.f32x2 %0, %1, %2, %3;" : "=l"(acc[i][0]) : "l"(A), "l"(B0), "l"(acc[i][0]));
                asm("fma.rn.f32x2 %0, %1, %2, %3;" : "=l"(acc[i][1]) : "l"(A), "l"(B1), "l"(acc[i][1]));
                asm("fma.rn.f32x2 %0, %1, %2, %3;" : "=l"(acc[i][2]) : "l"(A), "l"(B2), "l"(acc[i][2]));
                asm("fma.rn.f32x2 %0, %1, %2, %3;" : "=l"(acc[i][3]) : "l"(A), "l"(B3), "l"(acc[i][3]));
            }
        }
    }

    float d[8][8];
    #pragma unroll
    for (int i = 0; i < 8; i++)
        #pragma unroll
        for (int j = 0; j < 4; j++) {
            float lo, hi;
            asm("mov.b64 {%0, %1}, %2;" : "=f"(lo), "=f"(hi) : "l"(acc[i][j]));
            d[i][2 * j] = lo; d[i][2 * j + 1] = hi;
        }

    int qg0 = q0 + ty * 8, mg0 = m0 + tx * 8;
    float sqq[8], sqm[8];
    #pragma unroll
    for (int i = 0; i < 8; i++) {
        sqq[i] = g_sq[b * NN + qg0 + i];
        sqm[i] = g_sq[b * NN + mg0 + i];
    }
    #pragma unroll
    for (int i = 0; i < 8; i++)
        #pragma unroll
        for (int j = 0; j < 8; j++) {
            float v = (sqq[i] + sqm[j]) - 2.0f * d[i][j];
            d[i][j] = (diag && (qg0 + i == mg0 + j)) ? FLT_MAX : v;
        }

    // truncate to bf16 (monotone) and pack: out.lo16 = hi16(f0), out.hi16 = hi16(f1)
    __nv_bfloat16* hbase = g_d2h + ((size_t)b << 24);
    #pragma unroll
    for (int i = 0; i < 8; i++) {
        uint4 pk;
        pk.x = __byte_perm(__float_as_uint(d[i][0]), __float_as_uint(d[i][1]), 0x7632);
        pk.y = __byte_perm(__float_as_uint(d[i][2]), __float_as_uint(d[i][3]), 0x7632);
        pk.z = __byte_perm(__float_as_uint(d[i][4]), __float_as_uint(d[i][5]), 0x7632);
        pk.w = __byte_perm(__float_as_uint(d[i][6]), __float_as_uint(d[i][7]), 0x7632);
        *(uint4*)(hbase + (size_t)(qg0 + i) * NN + mg0) = pk;
    }
    if (!diag) {
        #pragma unroll
        for (int j = 0; j < 8; j++) {
            uint4 pk;
            pk.x = __byte_perm(__float_as_uint(d[0][j]), __float_as_uint(d[1][j]), 0x7632);
            pk.y = __byte_perm(__float_as_uint(d[2][j]), __float_as_uint(d[3][j]), 0x7632);
            pk.z = __byte_perm(__float_as_uint(d[4][j]), __float_as_uint(d[5][j]), 0x7632);
            pk.w = __byte_perm(__float_as_uint(d[6][j]), __float_as_uint(d[7][j]), 0x7632);
            *(uint4*)(hbase + (size_t)(mg0 + j) * NN + qg0) = pk;
        }
    }
}

// ---------------- K_select: bf16 screen + recompute-refine, exact top-20 set ----------------
#define INSP(v) do { __nv_bfloat162 t = (v); \
    __nv_bfloat162 n0 = __hmin2(t, p0); t = __hmax2(t, p0); p0 = n0; \
    __nv_bfloat162 n1 = __hmin2(t, p1); t = __hmax2(t, p1); p1 = n1; \
    __nv_bfloat162 n2 = __hmin2(t, p2); t = __hmax2(t, p2); p2 = n2; \
    p3 = __hmin2(t, p3); } while (0)

#define CAS(x, y) do { float _t = fminf(x, y); y = fmaxf(x, y); x = _t; } while (0)

__global__ __launch_bounds__(256) void k_select() {
    __shared__ int qq[8][66];
    int warp = threadIdx.x >> 5;
    int row  = (blockIdx.x << 3) + warp;                 // b*N + n
    int zbase = row & ~(NN - 1);
    int lane = threadIdx.x & 31;
    unsigned ltmask = (1u << lane) - 1u;
    const uint4* hr4 = (const uint4*)(g_d2h + (size_t)row * NN);

    // phase 1: packed bf16x2 top-4 per half-lane (depth 8 total)
    unsigned inf2b = 0x7F807F80u;
    __nv_bfloat162 p0, p1, p2, p3;
    p0 = p1 = p2 = p3 = *reinterpret_cast<__nv_bfloat162*>(&inf2b);
    #pragma unroll 4
    for (int e = 0; e < 16; e++) {
        uint4 r = hr4[e * 32 + lane];
        __nv_bfloat162 v0 = *reinterpret_cast<__nv_bfloat162*>(&r.x);
        __nv_bfloat162 v1 = *reinterpret_cast<__nv_bfloat162*>(&r.y);
        __nv_bfloat162 v2 = *reinterpret_cast<__nv_bfloat162*>(&r.z);
        __nv_bfloat162 v3 = *reinterpret_cast<__nv_bfloat162*>(&r.w);
        INSP(v0); INSP(v1); INSP(v2); INSP(v3);
    }

    // bitonic merge of two sorted-4 chains -> sorted 8
    float a0 = __low2float(p0),  a1 = __low2float(p1);
    float a2 = __low2float(p2),  a3 = __low2float(p3);
    float a4 = __high2float(p3), a5 = __high2float(p2);
    float a6 = __high2float(p1), a7 = __high2float(p0);
    CAS(a0, a4); CAS(a1, a5); CAS(a2, a6); CAS(a3, a7);
    CAS(a0, a2); CAS(a1, a3); CAS(a4, a6); CAS(a5, a7);
    CAS(a0, a1); CAS(a2, a3); CAS(a4, a5); CAS(a6, a7);

    // phase 2: 20 extraction rounds -> candidate bf16 threshold T
    float T = 0.f;
    for (int r = 0; r < KK; r++) {
        float w = a0;
        #pragma unroll
        for (int s = 16; s; s >>= 1)
            w = fminf(w, __shfl_xor_sync(0xFFFFFFFFu, w, s));
        unsigned msk = __ballot_sync(0xFFFFFFFFu, a0 == w);
        if (lane == __ffs(msk) - 1) {
            a0 = a1; a1 = a2; a2 = a3; a3 = a4;
            a4 = a5; a5 = a6; a6 = a7; a7 = FLT_MAX;
        }
        T = w;
    }

    // pass A: packed counts of (<=T), plus active-iter bitmap
    __nv_bfloat16  tb = __float2bfloat16(T);
    __nv_bfloat162 Tp = __bfloat162bfloat162(tb);
    __nv_bfloat162 accLE = __floats2bfloat162_rn(0.f, 0.f);
    unsigned bm = 0;
    #pragma unroll 4
    for (int e = 0; e < 16; e++) {
        uint4 r = hr4[e * 32 + lane];
        __nv_bfloat162 v0 = *reinterpret_cast<__nv_bfloat162*>(&r.x);
        __nv_bfloat162 v1 = *reinterpret_cast<__nv_bfloat162*>(&r.y);
        __nv_bfloat162 v2 = *reinterpret_cast<__nv_bfloat162*>(&r.z);
        __nv_bfloat162 v3 = *reinterpret_cast<__nv_bfloat162*>(&r.w);
        __nv_bfloat162 s = __hadd2(__hadd2(__hle2(v0, Tp), __hle2(v1, Tp)),
                                   __hadd2(__hle2(v2, Tp), __hle2(v3, Tp)));
        accLE = __hadd2(accLE, s);
        if (__low2float(s) + __high2float(s) > 0.f) bm |= 1u << e;
    }
    float2 fle = __bfloat1622float2(accLE);
    int lec = (int)(fle.x + fle.y);
    int pre = lec;
    #pragma unroll
    for (int s = 1; s < 32; s <<= 1) {
        int n = __shfl_up_sync(0xFFFFFFFFu, pre, s);
        if (lane >= s) pre += n;
    }
    int LEtot = __shfl_sync(0xFFFFFFFFu, pre, 31);
    int off   = pre - lec;

    if (LEtot <= 64) {
        // pass B: write candidate indices (only active iters; L1-hot)
        while (bm) {
            int e = __ffs(bm) - 1; bm &= bm - 1;
            uint4 r = hr4[e * 32 + lane];
            int base = (e * 32 + lane) * 8;
            __nv_bfloat162 v0 = *reinterpret_cast<__nv_bfloat162*>(&r.x);
            __nv_bfloat162 v1 = *reinterpret_cast<__nv_bfloat162*>(&r.y);
            __nv_bfloat162 v2 = *reinterpret_cast<__nv_bfloat162*>(&r.z);
            __nv_bfloat162 v3 = *reinterpret_cast<__nv_bfloat162*>(&r.w);
            if (__low2float(v0)  <= T) qq[warp][off++] = base;
            if (__high2float(v0) <= T) qq[warp][off++] = base + 1;
            if (__low2float(v1)  <= T) qq[warp][off++] = base + 2;
            if (__high2float(v1) <= T) qq[warp][off++] = base + 3;
            if (__low2float(v2)  <= T) qq[warp][off++] = base + 4;
            if (__high2float(v2) <= T) qq[warp][off++] = base + 5;
            if (__low2float(v3)  <= T) qq[warp][off++] = base + 6;
            if (__high2float(v3) <= T) qq[warp][off++] = base + 7;
        }
        __syncwarp();

        if (LEtot <= 32) {
            // common path: recompute fp32 for candidates, exclude (LEtot-20) largest
            unsigned long long key = 0ull;
            if (lane < LEtot) {
                int idx = qq[warp][lane];
                key = sortable_key(recompute_d(row, zbase, idx), (unsigned)idx);
            }
            int rem = LEtot - KK;
            for (int r = 0; r < rem; r++) {
                unsigned long long w = key;
                #pragma unroll
                for (int s = 16; s; s >>= 1) {
                    unsigned long long o = __shfl_xor_sync(0xFFFFFFFFu, w, s);
                    if (o > w) w = o;
                }
                unsigned msk = __ballot_sync(0xFFFFFFFFu, key == w);
                if (lane == __ffs(msk) - 1) key = 0ull;
            }
            unsigned vm = __ballot_sync(0xFFFFFFFFu, key != 0ull);
            if (key) g_idx[row * KK + __popc(vm & ltmask)] = (int)(key & 0xFFFFFFFFu);
        } else {
            // mid path: two keys per lane, 20 min-extraction rounds
            unsigned long long k0 = 0xFFFFFFFFFFFFFFFFull, k1 = 0xFFFFFFFFFFFFFFFFull;
            {
                int idx = qq[warp][lane];
                k0 = sortable_key(recompute_d(row, zbase, idx), (unsigned)idx);
            }
            if (lane + 32 < LEtot) {
                int idx = qq[warp][lane + 32];
                k1 = sortable_key(recompute_d(row, zbase, idx), (unsigned)idx);
            }
            for (int r = 0; r < KK; r++) {
                unsigned long long mn = k0 < k1 ? k0 : k1;
                unsigned long long w = mn;
                #pragma unroll
                for (int s = 16; s; s >>= 1) {
                    unsigned long long o = __shfl_xor_sync(0xFFFFFFFFu, w, s);
                    if (o < w) w = o;
                }
                unsigned msk = __ballot_sync(0xFFFFFFFFu, (k0 == w) || (k1 == w));
                if (lane == __ffs(msk) - 1) {
                    if (k0 == w) k0 = 0xFFFFFFFFFFFFFFFFull;
                    else         k1 = 0xFFFFFFFFFFFFFFFFull;
                }
                if (lane == 0) g_idx[row * KK + r] = (int)(w & 0xFFFFFFFFu);
            }
        }
    } else {
        // slow exact path (probability ~0): on-the-fly recompute extraction
        unsigned long long last = 0ull;
        for (int r = 0; r < KK; r++) {
            unsigned long long lmn = 0xFFFFFFFFFFFFFFFFull;
            for (int e = 0; e < 16; e++) {
                uint4 rr = hr4[e * 32 + lane];
                int base = (e * 32 + lane) * 8;
                unsigned short hv[8];
                hv[0] = (unsigned short)(rr.x & 0xFFFF); hv[1] = (unsigned short)(rr.x >> 16);
                hv[2] = (unsigned short)(rr.y & 0xFFFF); hv[3] = (unsigned short)(rr.y >> 16);
                hv[4] = (unsigned short)(rr.z & 0xFFFF); hv[5] = (unsigned short)(rr.z >> 16);
                hv[6] = (unsigned short)(rr.w & 0xFFFF); hv[7] = (unsigned short)(rr.w >> 16);
                for (int t = 0; t < 8; t++) {
                    __nv_bfloat16 hb = *reinterpret_cast<__nv_bfloat16*>(&hv[t]);
                    if (__bfloat162float(hb) <= T) {
                        int idx = base + t;
                        unsigned long long k =
                            sortable_key(recompute_d(row, zbase, idx), (unsigned)idx);
                        if (k > last && k < lmn) lmn = k;
                    }
                }
            }
            unsigned long long w = lmn;
            #pragma unroll
            for (int s = 16; s; s >>= 1) {
                unsigned long long o = __shfl_xor_sync(0xFFFFFFFFu, w, s);
                if (o < w) w = o;
            }
            if (lane == 0) g_idx[row * KK + r] = (int)(w & 0xFFFFFFFFu);
            last = w;
        }
    }
}

// ---------------- K_gather: ymax + BN stats ----------------
__global__ __launch_bounds__(256) void k_gather() {
    __shared__ float s[256];
    int tid = threadIdx.x;
    int pl = tid >> 6, o = tid & 63;
    float rs1 = 0.f, rs2 = 0.f;

    #pragma unroll
    for (int it = 0; it < 4; it++) {
        int pt = blockIdx.x * 16 + it * 4 + pl;
        int zbase = pt & ~(NN - 1);
        float u = g_u[(size_t)pt * OO + o];
        float m = -FLT_MAX, s1 = 0.f, s2 = 0.f;
        #pragma unroll
        for (int k = 0; k < KK; k++) {
            int nbr = __ldg(&g_idx[pt * KK + k]);
            float z = g_z[(size_t)(zbase + nbr) * OO + o];
            m = fmaxf(m, z);
            s1 += z;
            s2 = fmaf(z, z, s2);
        }
        g_ymax[(size_t)pt * OO + o] = u + m;
        rs1 += 20.f * u + s1;
        rs2 += fmaf(20.f * u, u, fmaf(2.f * u, s1, s2));
    }
    s[tid] = rs1; __syncthreads();
    if (pl == 0) atomicAdd(&g_sum[o], s[o] + s[o + 64] + s[o + 128] + s[o + 192]);
    __syncthreads();
    s[tid] = rs2; __syncthreads();
    if (pl == 0) atomicAdd(&g_sumsq[o], s[o] + s[o + 64] + s[o + 128] + s[o + 192]);
}

// ---------------- K_final: stats + normalize + relu + transpose ----------------
__global__ __launch_bounds__(256) void k_final(const float* __restrict__ gamma,
                                               const float* __restrict__ beta,
                                               float* __restrict__ out) {
    __shared__ float t[64][33];
    __shared__ float ssc[64], ssh[64];
    int b  = blockIdx.x >> 7;
    int n0 = (blockIdx.x & 127) << 5;
    int tid = threadIdx.x;

    if (tid < 64) {
        float mean = g_sum[tid] / BNK;
        float var  = g_sumsq[tid] / BNK - mean * mean;
        float sc   = gamma[tid] * rsqrtf(var + 1e-5f);
        ssc[tid] = sc;
        ssh[tid] = beta[tid] - mean * sc;
    }
    for (int i = tid; i < 2048; i += 256) {
        int r = i >> 6, c = i & 63;
        t[c][r] = g_ymax[(size_t)((b << 12) + n0 + r) * OO + c];
    }
    __syncthreads();
    for (int i = tid; i < 2048; i += 256) {
        int o = i >> 5, nl = i & 31;
        float v = fmaf(t[o][nl], ssc[o], ssh[o]);
        out[(size_t)b * OO * NN + (size_t)o * NN + n0 + nl] = fmaxf(v, 0.f);
    }
}

// ---------------- launch ----------------
extern "C" void kernel_launch(void* const* d_in, const int* in_sizes, int n_in,
                              void* d_out, int out_size) {
    const float* x     = (const float*)d_in[0];
    const float* W     = (const float*)d_in[1];
    const float* bias  = (const float*)d_in[2];
    const float* gamma = (const float*)d_in[3];
    const float* beta  = (const float*)d_in[4];
    float* out = (float*)d_out;

    k_prep<<<1024, 256>>>(x, W, bias);
    dim3 gd(32, 32, BB);
    k_dist<<<gd, 256>>>(x);
    k_select<<<BB * NN / 8, 256>>>();
    k_gather<<<2048, 256>>>();
    k_final<<<1024, 256>>>(gamma, beta, out);
}

// round 14
// speedup vs baseline: 1.3670x; 1.0063x over previous
#include <cuda_runtime.h>
#include <cuda_bf16.h>
#include <float.h>

// Problem constants
#define BB 8
#define CC 64
#define NN 4096
#define KK 20
#define OO 64
#define BNK 655360.0f   // B*N*K

// ---------------- static scratch ----------------
__device__ __nv_bfloat16 g_d2h[(size_t)BB * NN * NN];   // 268 MB truncated-bf16 distances
__device__ float g_xt[(size_t)BB * NN * CC];            // point-major x (8 MB, L2-resident)
__device__ float g_z[(size_t)BB * NN * OO];
__device__ float g_u[(size_t)BB * NN * OO];
__device__ float g_ymax[(size_t)BB * NN * OO];
__device__ float g_sq[BB * NN];
__device__ int   g_idx[BB * NN * KK];
__device__ float g_sum[OO];
__device__ float g_sumsq[OO];

// exact fp32 distance recompute from x_t (q, m within-batch; zbase = b*NN)
__device__ __forceinline__ float recompute_d(int row, int zbase, int m) {
    const float4* xq = (const float4*)(g_xt + (size_t)row * CC);
    const float4* xc = (const float4*)(g_xt + (size_t)(zbase + m) * CC);
    float acc = 0.f;
    #pragma unroll
    for (int c = 0; c < 16; c++) {
        float4 a = xq[c], b = xc[c];
        acc = fmaf(a.x, b.x, acc);
        acc = fmaf(a.y, b.y, acc);
        acc = fmaf(a.z, b.z, acc);
        acc = fmaf(a.w, b.w, acc);
    }
    return (g_sq[row] + g_sq[zbase + m]) - 2.0f * acc;
}

__device__ __forceinline__ unsigned long long sortable_key(float d, unsigned idx) {
    unsigned vb = __float_as_uint(d);
    unsigned u  = (vb & 0x80000000u) ? ~vb : (vb | 0x80000000u);
    return ((unsigned long long)u << 32) | idx;
}

// ---------------- K_prep: sq, z, u, x_t (+ zero stats) ----------------
__global__ __launch_bounds__(256) void k_prep(const float* __restrict__ x,
                                              const float* __restrict__ W,
                                              const float* __restrict__ bias) {
    __shared__ float xs[32][65];
    __shared__ float W2s[64][65];
    __shared__ float Wds[64][65];

    int blk = blockIdx.x;
    int b   = blk >> 7;
    int n0  = (blk & 127) * 32;
    int tid = threadIdx.x;

    if (blk == 0 && tid < OO) { g_sum[tid] = 0.f; g_sumsq[tid] = 0.f; }

    for (int i = tid; i < 64 * 64; i += 256) {
        int o = i >> 6, c = i & 63;
        float w1 = W[o * 128 + c];
        float w2 = W[o * 128 + 64 + c];
        W2s[o][c] = w2;
        Wds[o][c] = w1 - w2;
    }
    const float* xb = x + (size_t)b * CC * NN;
    for (int i = tid; i < 64 * 32; i += 256) {
        int c = i >> 5, j = i & 31;
        xs[j][c] = xb[c * NN + n0 + j];
    }
    __syncthreads();

    if (tid < 32) {
        float s = 0.f;
        #pragma unroll 16
        for (int c = 0; c < 64; c++) { float v = xs[tid][c]; s += v * v; }
        g_sq[b * NN + n0 + tid] = s;
    }

    // point-major x copy for refine recompute
    for (int i = tid; i < 2048; i += 256) {
        int j = i >> 6, c = i & 63;
        g_xt[(size_t)(b * NN + n0 + j) * CC + c] = xs[j][c];
    }

    for (int i = tid; i < 32 * 64; i += 256) {
        int j = i >> 6, o = i & 63;
        float za = 0.f, ua = bias[o];
        #pragma unroll 16
        for (int c = 0; c < 64; c++) {
            float xv = xs[j][c];
            za = fmaf(W2s[o][c], xv, za);
            ua = fmaf(Wds[o][c], xv, ua);
        }
        size_t pt = (size_t)(b * NN + n0 + j) * OO + o;
        g_z[pt] = za;
        g_u[pt] = ua;
    }
}

// ---------------- K_dist: symmetric pairwise d2, FFMA2, bf16-truncated output only ----------------
__global__ __launch_bounds__(256) void k_dist(const float* __restrict__ x) {
    int b  = blockIdx.z;
    int ti = blockIdx.y;
    int tj = blockIdx.x;
    if (tj < ti) return;
    bool diag = (tj == ti);

    __shared__ float sQ[32][128];
    __shared__ float sM[32][128];

    int q0 = ti * 128, m0 = tj * 128;
    int tid = threadIdx.x;
    int tx = tid & 15, ty = tid >> 4;

    unsigned long long acc[8][4];
    #pragma unroll
    for (int i = 0; i < 8; i++)
        #pragma unroll
        for (int j = 0; j < 4; j++) acc[i][j] = 0ull;

    for (int h = 0; h < 2; h++) {
        __syncthreads();
        const float* xb = x + ((size_t)b * CC + h * 32) * NN;
        for (int t = tid; t < 32 * 128; t += 256) {
            int c = t >> 7, n = t & 127;
            sQ[c][n] = xb[c * NN + q0 + n];
            sM[c][n] = xb[c * NN + m0 + n];
        }
        __syncthreads();

        #pragma unroll 8
        for (int c = 0; c < 32; c++) {
            float4 a0 = *(const float4*)&sQ[c][ty * 8];
            float4 a1 = *(const float4*)&sQ[c][ty * 8 + 4];
            ulonglong2 bb0 = *(const ulonglong2*)&sM[c][tx * 8];
            ulonglong2 bb1 = *(const ulonglong2*)&sM[c][tx * 8 + 4];
            unsigned long long B0 = bb0.x, B1 = bb0.y, B2 = bb1.x, B3 = bb1.y;
            float av[8] = {a0.x, a0.y, a0.z, a0.w, a1.x, a1.y, a1.z, a1.w};
            #pragma unroll
            for (int i = 0; i < 8; i++) {
                unsigned long long A;
                asm("mov.b64 %0, {%1, %1};" : "=l"(A) : "f"(av[i]));
                asm("fma.rn.f32x2 %0, %1, %2, %3;" : "=l"(acc[i][0]) : "l"(A), "l"(B0), "l"(acc[i][0]));
                asm("fma.rn.f32x2 %0, %1, %2, %3;" : "=l"(acc[i][1]) : "l"(A), "l"(B1), "l"(acc[i][1]));
                asm("fma.rn.f32x2 %0, %1, %2, %3;" : "=l"(acc[i][2]) : "l"(A), "l"(B2), "l"(acc[i][2]));
                asm("fma.rn.f32x2 %0, %1, %2, %3;" : "=l"(acc[i][3]) : "l"(A), "l"(B3), "l"(acc[i][3]));
            }
        }
    }

    float d[8][8];
    #pragma unroll
    for (int i = 0; i < 8; i++)
        #pragma unroll
        for (int j = 0; j < 4; j++) {
            float lo, hi;
            asm("mov.b64 {%0, %1}, %2;" : "=f"(lo), "=f"(hi) : "l"(acc[i][j]));
            d[i][2 * j] = lo; d[i][2 * j + 1] = hi;
        }

    int qg0 = q0 + ty * 8, mg0 = m0 + tx * 8;
    float sqq[8], sqm[8];
    #pragma unroll
    for (int i = 0; i < 8; i++) {
        sqq[i] = g_sq[b * NN + qg0 + i];
        sqm[i] = g_sq[b * NN + mg0 + i];
    }
    #pragma unroll
    for (int i = 0; i < 8; i++)
        #pragma unroll
        for (int j = 0; j < 8; j++) {
            float v = (sqq[i] + sqm[j]) - 2.0f * d[i][j];
            d[i][j] = (diag && (qg0 + i == mg0 + j)) ? FLT_MAX : v;
        }

    // truncate to bf16 (monotone) and pack
    __nv_bfloat16* hbase = g_d2h + ((size_t)b << 24);
    #pragma unroll
    for (int i = 0; i < 8; i++) {
        uint4 pk;
        pk.x = __byte_perm(__float_as_uint(d[i][0]), __float_as_uint(d[i][1]), 0x7632);
        pk.y = __byte_perm(__float_as_uint(d[i][2]), __float_as_uint(d[i][3]), 0x7632);
        pk.z = __byte_perm(__float_as_uint(d[i][4]), __float_as_uint(d[i][5]), 0x7632);
        pk.w = __byte_perm(__float_as_uint(d[i][6]), __float_as_uint(d[i][7]), 0x7632);
        *(uint4*)(hbase + (size_t)(qg0 + i) * NN + mg0) = pk;
    }
    if (!diag) {
        #pragma unroll
        for (int j = 0; j < 8; j++) {
            uint4 pk;
            pk.x = __byte_perm(__float_as_uint(d[0][j]), __float_as_uint(d[1][j]), 0x7632);
            pk.y = __byte_perm(__float_as_uint(d[2][j]), __float_as_uint(d[3][j]), 0x7632);
            pk.z = __byte_perm(__float_as_uint(d[4][j]), __float_as_uint(d[5][j]), 0x7632);
            pk.w = __byte_perm(__float_as_uint(d[6][j]), __float_as_uint(d[7][j]), 0x7632);
            *(uint4*)(hbase + (size_t)(mg0 + j) * NN + qg0) = pk;
        }
    }
}

// ---------------- K_select: bf16 screen (depth-2 packed) + exact recompute refine ----------------
// Correctness: extraction always yields T >= true 20th-smallest plane value, and
// the 20 popped elements prove count(plane <= T) >= 20. Refine recomputes exact
// fp32 for all candidates and selects the exact 20-set by (value,idx) key, so
// phase-1 cache depth only affects candidate-set size, never correctness.
#define INSP2(v) do { __nv_bfloat162 t = (v); \
    __nv_bfloat162 n0 = __hmin2(t, p0); t = __hmax2(t, p0); p0 = n0; \
    p1 = __hmin2(t, p1); } while (0)

#define CAS(x, y) do { float _t = fminf(x, y); y = fmaxf(x, y); x = _t; } while (0)

__global__ __launch_bounds__(256) void k_select() {
    __shared__ int qq[8][66];
    int warp = threadIdx.x >> 5;
    int row  = (blockIdx.x << 3) + warp;                 // b*N + n
    int zbase = row & ~(NN - 1);
    int lane = threadIdx.x & 31;
    unsigned ltmask = (1u << lane) - 1u;
    const uint4* hr4 = (const uint4*)(g_d2h + (size_t)row * NN);

    // phase 1: packed bf16x2 top-2 per half-lane (depth 4 total per lane)
    unsigned inf2b = 0x7F807F80u;
    __nv_bfloat162 p0, p1;
    p0 = p1 = *reinterpret_cast<__nv_bfloat162*>(&inf2b);
    #pragma unroll 4
    for (int e = 0; e < 16; e++) {
        uint4 r = hr4[e * 32 + lane];
        __nv_bfloat162 v0 = *reinterpret_cast<__nv_bfloat162*>(&r.x);
        __nv_bfloat162 v1 = *reinterpret_cast<__nv_bfloat162*>(&r.y);
        __nv_bfloat162 v2 = *reinterpret_cast<__nv_bfloat162*>(&r.z);
        __nv_bfloat162 v3 = *reinterpret_cast<__nv_bfloat162*>(&r.w);
        INSP2(v0); INSP2(v1); INSP2(v2); INSP2(v3);
    }

    // bitonic merge of sorted-2 even/odd chains -> sorted 4
    float a0 = __low2float(p0),  a1 = __low2float(p1);
    float a2 = __high2float(p1), a3 = __high2float(p0);
    CAS(a0, a2); CAS(a1, a3);
    CAS(a0, a1); CAS(a2, a3);

    // phase 2: 20 extraction rounds -> threshold T (>= true 20th plane value)
    float T = 0.f;
    for (int r = 0; r < KK; r++) {
        float w = a0;
        #pragma unroll
        for (int s = 16; s; s >>= 1)
            w = fminf(w, __shfl_xor_sync(0xFFFFFFFFu, w, s));
        unsigned msk = __ballot_sync(0xFFFFFFFFu, a0 == w);
        if (lane == __ffs(msk) - 1) {
            a0 = a1; a1 = a2; a2 = a3; a3 = FLT_MAX;
        }
        T = w;
    }
    __nv_bfloat16 tb = __float2bfloat16(T);   // T is an exact bf16 plane value
    float Tf = T;
    __nv_bfloat162 Tp = __bfloat162bfloat162(tb);

    // pass A: packed counts of (<= T), plus active-iter bitmap
    __nv_bfloat162 accLE = __floats2bfloat162_rn(0.f, 0.f);
    unsigned bm = 0;
    #pragma unroll 4
    for (int e = 0; e < 16; e++) {
        uint4 r = hr4[e * 32 + lane];
        __nv_bfloat162 v0 = *reinterpret_cast<__nv_bfloat162*>(&r.x);
        __nv_bfloat162 v1 = *reinterpret_cast<__nv_bfloat162*>(&r.y);
        __nv_bfloat162 v2 = *reinterpret_cast<__nv_bfloat162*>(&r.z);
        __nv_bfloat162 v3 = *reinterpret_cast<__nv_bfloat162*>(&r.w);
        __nv_bfloat162 s = __hadd2(__hadd2(__hle2(v0, Tp), __hle2(v1, Tp)),
                                   __hadd2(__hle2(v2, Tp), __hle2(v3, Tp)));
        accLE = __hadd2(accLE, s);
        if (__low2float(s) + __high2float(s) > 0.f) bm |= 1u << e;
    }
    float2 fle = __bfloat1622float2(accLE);
    int lec = (int)(fle.x + fle.y);
    int pre = lec;
    #pragma unroll
    for (int s = 1; s < 32; s <<= 1) {
        int n = __shfl_up_sync(0xFFFFFFFFu, pre, s);
        if (lane >= s) pre += n;
    }
    int LEtot = __shfl_sync(0xFFFFFFFFu, pre, 31);
    int off   = pre - lec;

    if (LEtot <= 64) {
        // pass B: write candidate indices (only active iters; L1-hot)
        while (bm) {
            int e = __ffs(bm) - 1; bm &= bm - 1;
            uint4 r = hr4[e * 32 + lane];
            int base = (e * 32 + lane) * 8;
            __nv_bfloat162 v0 = *reinterpret_cast<__nv_bfloat162*>(&r.x);
            __nv_bfloat162 v1 = *reinterpret_cast<__nv_bfloat162*>(&r.y);
            __nv_bfloat162 v2 = *reinterpret_cast<__nv_bfloat162*>(&r.z);
            __nv_bfloat162 v3 = *reinterpret_cast<__nv_bfloat162*>(&r.w);
            if (__low2float(v0)  <= Tf) qq[warp][off++] = base;
            if (__high2float(v0) <= Tf) qq[warp][off++] = base + 1;
            if (__low2float(v1)  <= Tf) qq[warp][off++] = base + 2;
            if (__high2float(v1) <= Tf) qq[warp][off++] = base + 3;
            if (__low2float(v2)  <= Tf) qq[warp][off++] = base + 4;
            if (__high2float(v2) <= Tf) qq[warp][off++] = base + 5;
            if (__low2float(v3)  <= Tf) qq[warp][off++] = base + 6;
            if (__high2float(v3) <= Tf) qq[warp][off++] = base + 7;
        }
        __syncwarp();

        if (LEtot <= 32) {
            // common path: exact recompute, exclude (LEtot-20) largest keys
            unsigned long long key = 0ull;
            if (lane < LEtot) {
                int idx = qq[warp][lane];
                key = sortable_key(recompute_d(row, zbase, idx), (unsigned)idx);
            }
            int rem = LEtot - KK;
            for (int r = 0; r < rem; r++) {
                unsigned long long w = key;
                #pragma unroll
                for (int s = 16; s; s >>= 1) {
                    unsigned long long o = __shfl_xor_sync(0xFFFFFFFFu, w, s);
                    if (o > w) w = o;
                }
                unsigned msk = __ballot_sync(0xFFFFFFFFu, key == w);
                if (lane == __ffs(msk) - 1) key = 0ull;
            }
            unsigned vm = __ballot_sync(0xFFFFFFFFu, key != 0ull);
            if (key) g_idx[row * KK + __popc(vm & ltmask)] = (int)(key & 0xFFFFFFFFu);
        } else {
            // mid path: two keys per lane, 20 min-extraction rounds
            unsigned long long k0 = 0xFFFFFFFFFFFFFFFFull, k1 = 0xFFFFFFFFFFFFFFFFull;
            {
                int idx = qq[warp][lane];
                k0 = sortable_key(recompute_d(row, zbase, idx), (unsigned)idx);
            }
            if (lane + 32 < LEtot) {
                int idx = qq[warp][lane + 32];
                k1 = sortable_key(recompute_d(row, zbase, idx), (unsigned)idx);
            }
            for (int r = 0; r < KK; r++) {
                unsigned long long mn = k0 < k1 ? k0 : k1;
                unsigned long long w = mn;
                #pragma unroll
                for (int s = 16; s; s >>= 1) {
                    unsigned long long o = __shfl_xor_sync(0xFFFFFFFFu, w, s);
                    if (o < w) w = o;
                }
                unsigned msk = __ballot_sync(0xFFFFFFFFu, (k0 == w) || (k1 == w));
                if (lane == __ffs(msk) - 1) {
                    if (k0 == w) k0 = 0xFFFFFFFFFFFFFFFFull;
                    else         k1 = 0xFFFFFFFFFFFFFFFFull;
                }
                if (lane == 0) g_idx[row * KK + r] = (int)(w & 0xFFFFFFFFu);
            }
        }
    } else {
        // slow exact path (very rare): on-the-fly recompute extraction
        unsigned long long last = 0ull;
        for (int r = 0; r < KK; r++) {
            unsigned long long lmn = 0xFFFFFFFFFFFFFFFFull;
            for (int e = 0; e < 16; e++) {
                uint4 rr = hr4[e * 32 + lane];
                int base = (e * 32 + lane) * 8;
                unsigned short hv[8];
                hv[0] = (unsigned short)(rr.x & 0xFFFF); hv[1] = (unsigned short)(rr.x >> 16);
                hv[2] = (unsigned short)(rr.y & 0xFFFF); hv[3] = (unsigned short)(rr.y >> 16);
                hv[4] = (unsigned short)(rr.z & 0xFFFF); hv[5] = (unsigned short)(rr.z >> 16);
                hv[6] = (unsigned short)(rr.w & 0xFFFF); hv[7] = (unsigned short)(rr.w >> 16);
                for (int t = 0; t < 8; t++) {
                    __nv_bfloat16 hb = *reinterpret_cast<__nv_bfloat16*>(&hv[t]);
                    if (__bfloat162float(hb) <= Tf) {
                        int idx = base + t;
                        unsigned long long k =
                            sortable_key(recompute_d(row, zbase, idx), (unsigned)idx);
                        if (k > last && k < lmn) lmn = k;
                    }
                }
            }
            unsigned long long w = lmn;
            #pragma unroll
            for (int s = 16; s; s >>= 1) {
                unsigned long long o = __shfl_xor_sync(0xFFFFFFFFu, w, s);
                if (o < w) w = o;
            }
            if (lane == 0) g_idx[row * KK + r] = (int)(w & 0xFFFFFFFFu);
            last = w;
        }
    }
}

// ---------------- K_gather: ymax + BN stats ----------------
__global__ __launch_bounds__(256) void k_gather() {
    __shared__ float s[256];
    int tid = threadIdx.x;
    int pl = tid >> 6, o = tid & 63;
    float rs1 = 0.f, rs2 = 0.f;

    #pragma unroll
    for (int it = 0; it < 4; it++) {
        int pt = blockIdx.x * 16 + it * 4 + pl;
        int zbase = pt & ~(NN - 1);
        float u = g_u[(size_t)pt * OO + o];
        float m = -FLT_MAX, s1 = 0.f, s2 = 0.f;
        #pragma unroll
        for (int k = 0; k < KK; k++) {
            int nbr = __ldg(&g_idx[pt * KK + k]);
            float z = g_z[(size_t)(zbase + nbr) * OO + o];
            m = fmaxf(m, z);
            s1 += z;
            s2 = fmaf(z, z, s2);
        }
        g_ymax[(size_t)pt * OO + o] = u + m;
        rs1 += 20.f * u + s1;
        rs2 += fmaf(20.f * u, u, fmaf(2.f * u, s1, s2));
    }
    s[tid] = rs1; __syncthreads();
    if (pl == 0) atomicAdd(&g_sum[o], s[o] + s[o + 64] + s[o + 128] + s[o + 192]);
    __syncthreads();
    s[tid] = rs2; __syncthreads();
    if (pl == 0) atomicAdd(&g_sumsq[o], s[o] + s[o + 64] + s[o + 128] + s[o + 192]);
}

// ---------------- K_final: stats + normalize + relu + transpose ----------------
__global__ __launch_bounds__(256) void k_final(const float* __restrict__ gamma,
                                               const float* __restrict__ beta,
                                               float* __restrict__ out) {
    __shared__ float t[64][33];
    __shared__ float ssc[64], ssh[64];
    int b  = blockIdx.x >> 7;
    int n0 = (blockIdx.x & 127) << 5;
    int tid = threadIdx.x;

    if (tid < 64) {
        float mean = g_sum[tid] / BNK;
        float var  = g_sumsq[tid] / BNK - mean * mean;
        float sc   = gamma[tid] * rsqrtf(var + 1e-5f);
        ssc[tid] = sc;
        ssh[tid] = beta[tid] - mean * sc;
    }
    for (int i = tid; i < 2048; i += 256) {
        int r = i >> 6, c = i & 63;
        t[c][r] = g_ymax[(size_t)((b << 12) + n0 + r) * OO + c];
    }
    __syncthreads();
    for (int i = tid; i < 2048; i += 256) {
        int o = i >> 5, nl = i & 31;
        float v = fmaf(t[o][nl], ssc[o], ssh[o]);
        out[(size_t)b * OO * NN + (size_t)o * NN + n0 + nl] = fmaxf(v, 0.f);
    }
}

// ---------------- launch ----------------
extern "C" void kernel_launch(void* const* d_in, const int* in_sizes, int n_in,
                              void* d_out, int out_size) {
    const float* x     = (const float*)d_in[0];
    const float* W     = (const float*)d_in[1];
    const float* bias  = (const float*)d_in[2];
    const float* gamma = (const float*)d_in[3];
    const float* beta  = (const float*)d_in[4];
    float* out = (float*)d_out;

    k_prep<<<1024, 256>>>(x, W, bias);
    dim3 gd(32, 32, BB);
    k_dist<<<gd, 256>>>(x);
    k_select<<<BB * NN / 8, 256>>>();
    k_gather<<<2048, 256>>>();
    k_final<<<1024, 256>>>(gamma, beta, out);
}

// round 16
// speedup vs baseline: 1.5030x; 1.0995x over previous
#include <cuda_runtime.h>
#include <cuda_bf16.h>
#include <float.h>

// Problem constants
#define BB 8
#define CC 64
#define NN 4096
#define KK 20
#define OO 64
#define BNK 655360.0f   // B*N*K

// ---------------- static scratch ----------------
__device__ __nv_bfloat16 g_d2h[(size_t)BB * NN * NN];   // 268 MB bf16 distance plane (approx)
__device__ __nv_bfloat16 g_xbf[(size_t)BB * NN * CC];   // point-major bf16 x (4.2 MB, L2-resident)
__device__ float g_xt[(size_t)BB * NN * CC];            // point-major fp32 x (exact refine)
__device__ float g_z[(size_t)BB * NN * OO];
__device__ float g_u[(size_t)BB * NN * OO];
__device__ float g_ymax[(size_t)BB * NN * OO];
__device__ float g_sq[BB * NN];
__device__ float g_sqmax[BB];
__device__ int   g_idx[BB * NN * KK];
__device__ float g_sum[OO];
__device__ float g_sumsq[OO];

// ---------------- helpers ----------------
__device__ __forceinline__ unsigned smem_u32(const void* p) {
    unsigned a;
    asm("{ .reg .u64 t; cvta.to.shared.u64 t, %1; cvt.u32.u64 %0, t; }" : "=r"(a) : "l"(p));
    return a;
}

// exact fp32 distance recompute from x_t
__device__ __forceinline__ float recompute_d(int row, int zbase, int m) {
    const float4* xq = (const float4*)(g_xt + (size_t)row * CC);
    const float4* xc = (const float4*)(g_xt + (size_t)(zbase + m) * CC);
    float acc = 0.f;
    #pragma unroll
    for (int c = 0; c < 16; c++) {
        float4 a = xq[c], b = xc[c];
        acc = fmaf(a.x, b.x, acc);
        acc = fmaf(a.y, b.y, acc);
        acc = fmaf(a.z, b.z, acc);
        acc = fmaf(a.w, b.w, acc);
    }
    return (g_sq[row] + g_sq[zbase + m]) - 2.0f * acc;
}

__device__ __forceinline__ unsigned long long sortable_key(float d, unsigned idx) {
    unsigned vb = __float_as_uint(d);
    unsigned u  = (vb & 0x80000000u) ? ~vb : (vb | 0x80000000u);
    return ((unsigned long long)u << 32) | idx;
}

// ---------------- K_prep: sq, z, u, x_t, x_bf (+ zero stats) ----------------
__global__ __launch_bounds__(256) void k_prep(const float* __restrict__ x,
                                              const float* __restrict__ W,
                                              const float* __restrict__ bias) {
    __shared__ float xs[32][65];
    __shared__ float W2s[64][65];
    __shared__ float Wds[64][65];

    int blk = blockIdx.x;
    int b   = blk >> 7;
    int n0  = (blk & 127) * 32;
    int tid = threadIdx.x;

    if (blk == 0 && tid < OO) { g_sum[tid] = 0.f; g_sumsq[tid] = 0.f; }

    for (int i = tid; i < 64 * 64; i += 256) {
        int o = i >> 6, c = i & 63;
        float w1 = W[o * 128 + c];
        float w2 = W[o * 128 + 64 + c];
        W2s[o][c] = w2;
        Wds[o][c] = w1 - w2;
    }
    const float* xb = x + (size_t)b * CC * NN;
    for (int i = tid; i < 64 * 32; i += 256) {
        int c = i >> 5, j = i & 31;
        xs[j][c] = xb[c * NN + n0 + j];
    }
    __syncthreads();

    if (tid < 32) {
        float s = 0.f;
        #pragma unroll 16
        for (int c = 0; c < 64; c++) { float v = xs[tid][c]; s += v * v; }
        g_sq[b * NN + n0 + tid] = s;
    }

    for (int i = tid; i < 2048; i += 256) {
        int j = i >> 6, c = i & 63;
        float v = xs[j][c];
        size_t p = (size_t)(b * NN + n0 + j) * CC + c;
        g_xt[p]  = v;
        g_xbf[p] = __float2bfloat16_rn(v);
    }

    for (int i = tid; i < 32 * 64; i += 256) {
        int j = i >> 6, o = i & 63;
        float za = 0.f, ua = bias[o];
        #pragma unroll 16
        for (int c = 0; c < 64; c++) {
            float xv = xs[j][c];
            za = fmaf(W2s[o][c], xv, za);
            ua = fmaf(Wds[o][c], xv, ua);
        }
        size_t pt = (size_t)(b * NN + n0 + j) * OO + o;
        g_z[pt] = za;
        g_u[pt] = ua;
    }
}

// ---------------- K_sqmax: per-batch max of |x|^2 ----------------
__global__ __launch_bounds__(256) void k_sqmax() {
    __shared__ float sm[256];
    int b = blockIdx.x, tid = threadIdx.x;
    float m = 0.f;
    for (int i = tid; i < NN; i += 256) m = fmaxf(m, g_sq[b * NN + i]);
    sm[tid] = m; __syncthreads();
    for (int s = 128; s; s >>= 1) {
        if (tid < s) sm[tid] = fmaxf(sm[tid], sm[tid + s]);
        __syncthreads();
    }
    if (tid == 0) g_sqmax[b] = sm[0];
}

// ---------------- K_dist_mma: ldmatrix + mma.sync bf16 128x128 tile ----------------
// full grid (no symmetry); A/B = bf16 x tiles (128 pts x 64 ch, SW128 swizzle).
// warp grid 4x2: warp tile 32q x 64m; m16n8k16 frags, fp32 accum.
__global__ __launch_bounds__(256) void k_dist_mma() {
    __shared__ __align__(16) unsigned char sbuf[34816];  // A(16K)+B(16K); reused as 128x272B staging
    __shared__ float ssqq[128], ssqm[128];

    unsigned char* sA = sbuf;
    unsigned char* sB = sbuf + 16384;

    int b  = blockIdx.z;
    int ti = blockIdx.y;          // q tile
    int tj = blockIdx.x;          // m tile
    int q0 = ti * 128, m0 = tj * 128;
    int tid = threadIdx.x, warp = tid >> 5, lane = tid & 31;
    int wm = (warp >> 1) * 32;    // warp q base
    int wn = (warp & 1) * 64;     // warp m base

    // load tiles (16B granules, SW128 swizzle: granule' = granule ^ (row&7))
    const uint4* gA = (const uint4*)(g_xbf + (size_t)(b * NN + q0) * CC);
    const uint4* gB = (const uint4*)(g_xbf + (size_t)(b * NN + m0) * CC);
    #pragma unroll
    for (int i = 0; i < 4; i++) {
        int lin = i * 256 + tid;                // 0..1023: row = lin>>3, granule = lin&7
        int row = lin >> 3, gr = lin & 7;
        unsigned sw = (unsigned)(row * 128 + ((gr ^ (row & 7)) << 4));
        *(uint4*)(sA + sw) = gA[lin];
        *(uint4*)(sB + sw) = gB[lin];
    }
    if (tid < 128) ssqq[tid] = g_sq[b * NN + q0 + tid];
    else           ssqm[tid - 128] = g_sq[b * NN + m0 + (tid - 128)];
    __syncthreads();

    unsigned sAu = smem_u32(sA), sBu = smem_u32(sB);

    // per-lane ldmatrix row terms
    int lr = lane & 7;
    int rowA0 = wm + lr + ((lane >> 3) & 1) * 8;          // mt=0
    int rowA1 = rowA0 + 16;                                // mt=1
    int colgA = lane >> 4;                                 // 0/1 -> k granule base
    unsigned baseA0 = sAu + rowA0 * 128;
    unsigned baseA1 = sAu + rowA1 * 128;
    int colgB = (lane >> 3) & 1;
    unsigned baseB[8];
    #pragma unroll
    for (int nt = 0; nt < 8; nt++)
        baseB[nt] = sBu + (wn + nt * 8 + lr) * 128;

    float acc[2][8][4];
    #pragma unroll
    for (int mt = 0; mt < 2; mt++)
        #pragma unroll
        for (int nt = 0; nt < 8; nt++)
            #pragma unroll
            for (int r = 0; r < 4; r++) acc[mt][nt][r] = 0.f;

    #pragma unroll
    for (int ks = 0; ks < 4; ks++) {
        int kga = colgA + ks * 2;
        int kgb = colgB + ks * 2;
        unsigned aoffs = (unsigned)((kga ^ lr) << 4);
        unsigned boffs = (unsigned)((kgb ^ lr) << 4);

        uint4 af[2];
        asm volatile("ldmatrix.sync.aligned.m8n8.x4.shared.b16 {%0,%1,%2,%3}, [%4];"
                     : "=r"(af[0].x), "=r"(af[0].y), "=r"(af[0].z), "=r"(af[0].w)
                     : "r"(baseA0 + aoffs));
        asm volatile("ldmatrix.sync.aligned.m8n8.x4.shared.b16 {%0,%1,%2,%3}, [%4];"
                     : "=r"(af[1].x), "=r"(af[1].y), "=r"(af[1].z), "=r"(af[1].w)
                     : "r"(baseA1 + aoffs));

        #pragma unroll
        for (int nt = 0; nt < 8; nt++) {
            uint2 bf;
            asm volatile("ldmatrix.sync.aligned.m8n8.x2.shared.b16 {%0,%1}, [%2];"
                         : "=r"(bf.x), "=r"(bf.y)
                         : "r"(baseB[nt] + boffs));
            #pragma unroll
            for (int mt = 0; mt < 2; mt++) {
                asm volatile(
                    "mma.sync.aligned.m16n8k16.row.col.f32.bf16.bf16.f32 "
                    "{%0,%1,%2,%3}, {%4,%5,%6,%7}, {%8,%9}, {%0,%1,%2,%3};"
                    : "+f"(acc[mt][nt][0]), "+f"(acc[mt][nt][1]),
                      "+f"(acc[mt][nt][2]), "+f"(acc[mt][nt][3])
                    : "r"(af[mt].x), "r"(af[mt].y), "r"(af[mt].z), "r"(af[mt].w),
                      "r"(bf.x), "r"(bf.y));
            }
        }
    }
    __syncthreads();   // done reading sA/sB; sbuf becomes staging

    // epilogue: d = sqq + sqm - 2*dot, truncate-pack bf16 pairs, stage (272B rows)
    bool diag = (ti == tj);
    int qrl = lane >> 2;           // 0..7
    int mcl = (lane & 3) * 2;
    #pragma unroll
    for (int mt = 0; mt < 2; mt++) {
        int r0 = wm + mt * 16 + qrl;
        int r1 = r0 + 8;
        float sq0 = ssqq[r0], sq1 = ssqq[r1];
        #pragma unroll
        for (int nt = 0; nt < 8; nt++) {
            int ml = wn + nt * 8 + mcl;
            float sm0 = ssqm[ml], sm1 = ssqm[ml + 1];
            float d00 = (sq0 + sm0) - 2.0f * acc[mt][nt][0];
            float d01 = (sq0 + sm1) - 2.0f * acc[mt][nt][1];
            float d10 = (sq1 + sm0) - 2.0f * acc[mt][nt][2];
            float d11 = (sq1 + sm1) - 2.0f * acc[mt][nt][3];
            if (diag) {
                if (r0 == ml)     d00 = 3.0e38f;
                if (r0 == ml + 1) d01 = 3.0e38f;
                if (r1 == ml)     d10 = 3.0e38f;
                if (r1 == ml + 1) d11 = 3.0e38f;
            }
            *(unsigned*)(sbuf + r0 * 272 + ml * 2) =
                __byte_perm(__float_as_uint(d00), __float_as_uint(d01), 0x7632);
            *(unsigned*)(sbuf + r1 * 272 + ml * 2) =
                __byte_perm(__float_as_uint(d10), __float_as_uint(d11), 0x7632);
        }
    }
    __syncthreads();

    // coalesced copy-out: 128 rows x 256 BYTES = 16 granules per row (R15 bug:
    // used 8 granules/row, leaving m-cols 64..127 unwritten)
    __nv_bfloat16* hbase = g_d2h + ((size_t)b << 24);
    #pragma unroll
    for (int i = 0; i < 8; i++) {
        int lin = i * 256 + tid;               // 0..2047: row = lin>>4, granule = lin&15
        int row = lin >> 4, gr = lin & 15;
        uint4 v = *(uint4*)(sbuf + row * 272 + gr * 16);
        *(uint4*)(hbase + (size_t)(q0 + row) * NN + m0 + gr * 8) = v;
    }
}

// ---------------- K_select: bf16 screen (+provable margin) + exact recompute refine ----------------
#define INSP2(v) do { __nv_bfloat162 t = (v); \
    __nv_bfloat162 n0 = __hmin2(t, p0); t = __hmax2(t, p0); p0 = n0; \
    p1 = __hmin2(t, p1); } while (0)

#define CAS(x, y) do { float _t = fminf(x, y); y = fmaxf(x, y); x = _t; } while (0)

__global__ __launch_bounds__(256) void k_select() {
    __shared__ int qq[8][100];
    int warp = threadIdx.x >> 5;
    int row  = (blockIdx.x << 3) + warp;                 // b*N + n
    int zbase = row & ~(NN - 1);
    int lane = threadIdx.x & 31;
    unsigned ltmask = (1u << lane) - 1u;
    const uint4* hr4 = (const uint4*)(g_d2h + (size_t)row * NN);

    // phase 1: packed bf16x2 top-2 per half-lane
    unsigned inf2b = 0x7F807F80u;
    __nv_bfloat162 p0, p1;
    p0 = p1 = *reinterpret_cast<__nv_bfloat162*>(&inf2b);
    #pragma unroll 4
    for (int e = 0; e < 16; e++) {
        uint4 r = hr4[e * 32 + lane];
        __nv_bfloat162 v0 = *reinterpret_cast<__nv_bfloat162*>(&r.x);
        __nv_bfloat162 v1 = *reinterpret_cast<__nv_bfloat162*>(&r.y);
        __nv_bfloat162 v2 = *reinterpret_cast<__nv_bfloat162*>(&r.z);
        __nv_bfloat162 v3 = *reinterpret_cast<__nv_bfloat162*>(&r.w);
        INSP2(v0); INSP2(v1); INSP2(v2); INSP2(v3);
    }

    // bitonic merge of sorted-2 even/odd chains -> sorted 4
    float a0 = __low2float(p0),  a1 = __low2float(p1);
    float a2 = __high2float(p1), a3 = __high2float(p0);
    CAS(a0, a2); CAS(a1, a3);
    CAS(a0, a1); CAS(a2, a3);

    // phase 2: 20 extraction rounds -> T >= true 20th plane value
    float T = 0.f;
    for (int r = 0; r < KK; r++) {
        float w = a0;
        #pragma unroll
        for (int s = 16; s; s >>= 1)
            w = fminf(w, __shfl_xor_sync(0xFFFFFFFFu, w, s));
        unsigned msk = __ballot_sync(0xFFFFFFFFu, a0 == w);
        if (lane == __ffs(msk) - 1) {
            a0 = a1; a1 = a2; a2 = a3; a3 = FLT_MAX;
        }
        T = w;
    }

    // provable screen threshold (covers bf16-input MMA error + truncation)
    int bidx = row >> 12;
    float theta = fmaf(T, 1.015625f,
                       fmaf(0.017f, sqrtf(g_sq[row] * g_sqmax[bidx]), 0.01f));
    __nv_bfloat16 tb = __float2bfloat16_ru(theta);
    float Tf = __bfloat162float(tb);
    __nv_bfloat162 Tp = __bfloat162bfloat162(tb);

    // pass A: packed counts of (<= Tf), plus active-iter bitmap
    __nv_bfloat162 accLE = __floats2bfloat162_rn(0.f, 0.f);
    unsigned bm = 0;
    #pragma unroll 4
    for (int e = 0; e < 16; e++) {
        uint4 r = hr4[e * 32 + lane];
        __nv_bfloat162 v0 = *reinterpret_cast<__nv_bfloat162*>(&r.x);
        __nv_bfloat162 v1 = *reinterpret_cast<__nv_bfloat162*>(&r.y);
        __nv_bfloat162 v2 = *reinterpret_cast<__nv_bfloat162*>(&r.z);
        __nv_bfloat162 v3 = *reinterpret_cast<__nv_bfloat162*>(&r.w);
        __nv_bfloat162 s = __hadd2(__hadd2(__hle2(v0, Tp), __hle2(v1, Tp)),
                                   __hadd2(__hle2(v2, Tp), __hle2(v3, Tp)));
        accLE = __hadd2(accLE, s);
        if (__low2float(s) + __high2float(s) > 0.f) bm |= 1u << e;
    }
    float2 fle = __bfloat1622float2(accLE);
    int lec = (int)(fle.x + fle.y);
    int pre = lec;
    #pragma unroll
    for (int s = 1; s < 32; s <<= 1) {
        int n = __shfl_up_sync(0xFFFFFFFFu, pre, s);
        if (lane >= s) pre += n;
    }
    int LEtot = __shfl_sync(0xFFFFFFFFu, pre, 31);
    int off   = pre - lec;

    if (LEtot <= 96) {
        // pass B: write candidate indices (active iters only; L1-hot)
        while (bm) {
            int e = __ffs(bm) - 1; bm &= bm - 1;
            uint4 r = hr4[e * 32 + lane];
            int base = (e * 32 + lane) * 8;
            __nv_bfloat162 v0 = *reinterpret_cast<__nv_bfloat162*>(&r.x);
            __nv_bfloat162 v1 = *reinterpret_cast<__nv_bfloat162*>(&r.y);
            __nv_bfloat162 v2 = *reinterpret_cast<__nv_bfloat162*>(&r.z);
            __nv_bfloat162 v3 = *reinterpret_cast<__nv_bfloat162*>(&r.w);
            if (__low2float(v0)  <= Tf) qq[warp][off++] = base;
            if (__high2float(v0) <= Tf) qq[warp][off++] = base + 1;
            if (__low2float(v1)  <= Tf) qq[warp][off++] = base + 2;
            if (__high2float(v1) <= Tf) qq[warp][off++] = base + 3;
            if (__low2float(v2)  <= Tf) qq[warp][off++] = base + 4;
            if (__high2float(v2) <= Tf) qq[warp][off++] = base + 5;
            if (__low2float(v3)  <= Tf) qq[warp][off++] = base + 6;
            if (__high2float(v3) <= Tf) qq[warp][off++] = base + 7;
        }
        __syncwarp();

        if (LEtot <= 32) {
            // exact recompute, exclude (LEtot-20) largest keys
            unsigned long long key = 0ull;
            if (lane < LEtot) {
                int idx = qq[warp][lane];
                key = sortable_key(recompute_d(row, zbase, idx), (unsigned)idx);
            }
            int rem = LEtot - KK;
            for (int r = 0; r < rem; r++) {
                unsigned long long w = key;
                #pragma unroll
                for (int s = 16; s; s >>= 1) {
                    unsigned long long o = __shfl_xor_sync(0xFFFFFFFFu, w, s);
                    if (o > w) w = o;
                }
                unsigned msk = __ballot_sync(0xFFFFFFFFu, key == w);
                if (lane == __ffs(msk) - 1) key = 0ull;
            }
            unsigned vm = __ballot_sync(0xFFFFFFFFu, key != 0ull);
            if (key) g_idx[row * KK + __popc(vm & ltmask)] = (int)(key & 0xFFFFFFFFu);
        } else {
            // mid path: up to 3 keys per lane, 20 min-extraction rounds
            const unsigned long long UMX = 0xFFFFFFFFFFFFFFFFull;
            unsigned long long k0 = UMX, k1 = UMX, k2 = UMX;
            {
                int idx = qq[warp][lane];
                k0 = sortable_key(recompute_d(row, zbase, idx), (unsigned)idx);
            }
            if (lane + 32 < LEtot) {
                int idx = qq[warp][lane + 32];
                k1 = sortable_key(recompute_d(row, zbase, idx), (unsigned)idx);
            }
            if (lane + 64 < LEtot) {
                int idx = qq[warp][lane + 64];
                k2 = sortable_key(recompute_d(row, zbase, idx), (unsigned)idx);
            }
            for (int r = 0; r < KK; r++) {
                unsigned long long mn = k0 < k1 ? k0 : k1;
                if (k2 < mn) mn = k2;
                unsigned long long w = mn;
                #pragma unroll
                for (int s = 16; s; s >>= 1) {
                    unsigned long long o = __shfl_xor_sync(0xFFFFFFFFu, w, s);
                    if (o < w) w = o;
                }
                unsigned msk = __ballot_sync(0xFFFFFFFFu, mn == w);
                if (lane == __ffs(msk) - 1) {
                    if (k0 == w) k0 = UMX;
                    else if (k1 == w) k1 = UMX;
                    else k2 = UMX;
                }
                if (lane == 0) g_idx[row * KK + r] = (int)(w & 0xFFFFFFFFu);
            }
        }
    } else {
        // slow exact path (rare): on-the-fly recompute extraction
        unsigned long long last = 0ull;
        for (int r = 0; r < KK; r++) {
            unsigned long long lmn = 0xFFFFFFFFFFFFFFFFull;
            for (int e = 0; e < 16; e++) {
                uint4 rr = hr4[e * 32 + lane];
                int base = (e * 32 + lane) * 8;
                unsigned short hv[8];
                hv[0] = (unsigned short)(rr.x & 0xFFFF); hv[1] = (unsigned short)(rr.x >> 16);
                hv[2] = (unsigned short)(rr.y & 0xFFFF); hv[3] = (unsigned short)(rr.y >> 16);
                hv[4] = (unsigned short)(rr.z & 0xFFFF); hv[5] = (unsigned short)(rr.z >> 16);
                hv[6] = (unsigned short)(rr.w & 0xFFFF); hv[7] = (unsigned short)(rr.w >> 16);
                for (int t = 0; t < 8; t++) {
                    __nv_bfloat16 hb = *reinterpret_cast<__nv_bfloat16*>(&hv[t]);
                    if (__bfloat162float(hb) <= Tf) {
                        int idx = base + t;
                        unsigned long long k =
                            sortable_key(recompute_d(row, zbase, idx), (unsigned)idx);
                        if (k > last && k < lmn) lmn = k;
                    }
                }
            }
            unsigned long long w = lmn;
            #pragma unroll
            for (int s = 16; s; s >>= 1) {
                unsigned long long o = __shfl_xor_sync(0xFFFFFFFFu, w, s);
                if (o < w) w = o;
            }
            if (lane == 0) g_idx[row * KK + r] = (int)(w & 0xFFFFFFFFu);
            last = w;
        }
    }
}

// ---------------- K_gather: ymax + BN stats ----------------
__global__ __launch_bounds__(256) void k_gather() {
    __shared__ float s[256];
    int tid = threadIdx.x;
    int pl = tid >> 6, o = tid & 63;
    float rs1 = 0.f, rs2 = 0.f;

    #pragma unroll
    for (int it = 0; it < 4; it++) {
        int pt = blockIdx.x * 16 + it * 4 + pl;
        int zbase = pt & ~(NN - 1);
        float u = g_u[(size_t)pt * OO + o];
        float m = -FLT_MAX, s1 = 0.f, s2 = 0.f;
        #pragma unroll
        for (int k = 0; k < KK; k++) {
            int nbr = __ldg(&g_idx[pt * KK + k]);
            float z = g_z[(size_t)(zbase + nbr) * OO + o];
            m = fmaxf(m, z);
            s1 += z;
            s2 = fmaf(z, z, s2);
        }
        g_ymax[(size_t)pt * OO + o] = u + m;
        rs1 += 20.f * u + s1;
        rs2 += fmaf(20.f * u, u, fmaf(2.f * u, s1, s2));
    }
    s[tid] = rs1; __syncthreads();
    if (pl == 0) atomicAdd(&g_sum[o], s[o] + s[o + 64] + s[o + 128] + s[o + 192]);
    __syncthreads();
    s[tid] = rs2; __syncthreads();
    if (pl == 0) atomicAdd(&g_sumsq[o], s[o] + s[o + 64] + s[o + 128] + s[o + 192]);
}

// ---------------- K_final: stats + normalize + relu + transpose ----------------
__global__ __launch_bounds__(256) void k_final(const float* __restrict__ gamma,
                                               const float* __restrict__ beta,
                                               float* __restrict__ out) {
    __shared__ float t[64][33];
    __shared__ float ssc[64], ssh[64];
    int b  = blockIdx.x >> 7;
    int n0 = (blockIdx.x & 127) << 5;
    int tid = threadIdx.x;

    if (tid < 64) {
        float mean = g_sum[tid] / BNK;
        float var  = g_sumsq[tid] / BNK - mean * mean;
        float sc   = gamma[tid] * rsqrtf(var + 1e-5f);
        ssc[tid] = sc;
        ssh[tid] = beta[tid] - mean * sc;
    }
    for (int i = tid; i < 2048; i += 256) {
        int r = i >> 6, c = i & 63;
        t[c][r] = g_ymax[(size_t)((b << 12) + n0 + r) * OO + c];
    }
    __syncthreads();
    for (int i = tid; i < 2048; i += 256) {
        int o = i >> 5, nl = i & 31;
        float v = fmaf(t[o][nl], ssc[o], ssh[o]);
        out[(size_t)b * OO * NN + (size_t)o * NN + n0 + nl] = fmaxf(v, 0.f);
    }
}

// ---------------- launch ----------------
extern "C" void kernel_launch(void* const* d_in, const int* in_sizes, int n_in,
                              void* d_out, int out_size) {
    const float* x     = (const float*)d_in[0];
    const float* W     = (const float*)d_in[1];
    const float* bias  = (const float*)d_in[2];
    const float* gamma = (const float*)d_in[3];
    const float* beta  = (const float*)d_in[4];
    float* out = (float*)d_out;

    k_prep<<<1024, 256>>>(x, W, bias);
    k_sqmax<<<BB, 256>>>();
    dim3 gd(32, 32, BB);
    k_dist_mma<<<gd, 256>>>();
    k_select<<<BB * NN / 8, 256>>>();
    k_gather<<<2048, 256>>>();
    k_final<<<1024, 256>>>(gamma, beta, out);
}